// round 13
// baseline (speedup 1.0000x reference)
#include <cuda_runtime.h>
#include <cuda_bf16.h>

// Persistent single-launch parallel-in-time undulator tracker.
// Analytic Picard-1 init (closed-form theta on secular ballistic path);
// final sweep replicates the reference's f32 quantized accumulation.
// R13: x/y quantized increments use ANALYTIC binade references (no plain-x
// scan) -> the three q-ladders fuse into ONE scan. 3 grid barriers total.

#define TPB 1024
#define GRD 148
#define EPT 7
#define TILE (TPB * EPT)          // 7168
#define CAP (TILE * GRD)          // 1,060,864

__device__ volatile unsigned g_gen;   // monotonic across graph replays
__device__ unsigned g_cnt;
__device__ volatile float  g_totf[2][GRD];
__device__ volatile float  g_totf2[2][GRD];
__device__ volatile double g_totd[2][GRD];

struct SCon {
    float kuf, Kthf, Kzf, phi0f, f0f, cyf, y0f, x0f, scalef, byc, vzmdtf;
    float aampf, spsi0f, vxmdtf, Coscf;
    double z0, vzmdt, x0, y0;
};

struct SMem {
    __align__(16) float stage[2][TILE];   // 56 KB output transpose buffers
    SCon c;
    float  wf[32], wf2[32];
    double wd[32];
    float  bf, bf2;
    double bd;
    unsigned base;
};

static __device__ __forceinline__ float warp_iscan_f(float v, int lane) {
#pragma unroll
    for (int d = 1; d < 32; d <<= 1) {
        float n = __shfl_up_sync(0xffffffffu, v, d);
        if (lane >= d) v += n;
    }
    return v;
}
static __device__ __forceinline__ double warp_iscan_d(double v, int lane) {
#pragma unroll
    for (int d = 1; d < 32; d <<= 1) {
        double n = __shfl_up_sync(0xffffffffu, v, d);
        if (lane >= d) v += n;
    }
    return v;
}
static __device__ __forceinline__ float warp_sum_f(float v) {
#pragma unroll
    for (int d = 16; d; d >>= 1) v += __shfl_down_sync(0xffffffffu, v, d);
    return v;
}
static __device__ __forceinline__ double warp_sum_d(double v) {
#pragma unroll
    for (int d = 16; d; d >>= 1) v += __shfl_down_sync(0xffffffffu, v, d);
    return v;
}

static __device__ __forceinline__ void grid_barrier(unsigned target) {
    __syncthreads();
    if (threadIdx.x == 0) {
        __threadfence();
        unsigned prev = atomicAdd(&g_cnt, 1u);
        if (prev == GRD - 1) {
            g_cnt = 0;
            __threadfence();
            g_gen = target;
        } else {
            while (g_gen != target) { }
            __threadfence();
        }
    }
    __syncthreads();
}

static __device__ float scan_f(SMem* sm, float tf, int sid, unsigned bg) {
    const int lane = threadIdx.x & 31, wid = threadIdx.x >> 5;
    const int buf = sid & 1;
    __syncthreads();
    float wf = warp_iscan_f(tf, lane);
    if (lane == 31) sm->wf[wid] = wf;
    __syncthreads();
    if (wid == 0) {
        float vf = sm->wf[lane];
        float sf = warp_iscan_f(vf, lane);
        sm->wf[lane] = sf - vf;
        if (lane == 31) g_totf[buf][blockIdx.x] = sf;
    }
    grid_barrier(bg + (unsigned)sid + 1u);
    if (wid == 0) {
        float af = 0.f;
#pragma unroll
        for (int j = lane; j < GRD; j += 32)
            if (j < (int)blockIdx.x) af += g_totf[buf][j];
        af = warp_sum_f(af);
        if (lane == 0) sm->bf = af;
    }
    __syncthreads();
    return sm->bf + sm->wf[wid] + (wf - tf);
}

static __device__ double scan_d(SMem* sm, double td, int sid, unsigned bg) {
    const int lane = threadIdx.x & 31, wid = threadIdx.x >> 5;
    const int buf = sid & 1;
    __syncthreads();
    double wd = warp_iscan_d(td, lane);
    if (lane == 31) sm->wd[wid] = wd;
    __syncthreads();
    if (wid == 0) {
        double vd = sm->wd[lane];
        double sd = warp_iscan_d(vd, lane);
        sm->wd[lane] = sd - vd;
        if (lane == 31) g_totd[buf][blockIdx.x] = sd;
    }
    grid_barrier(bg + (unsigned)sid + 1u);
    if (wid == 0) {
        double ad = 0.0;
#pragma unroll
        for (int j = lane; j < GRD; j += 32)
            if (j < (int)blockIdx.x) ad += g_totd[buf][j];
        ad = warp_sum_d(ad);
        if (lane == 0) sm->bd = ad;
    }
    __syncthreads();
    return sm->bd + sm->wd[wid] + (wd - td);
}

// Fused: one f64 chain + two f32 chains, ONE grid barrier.
static __device__ void scan_dff(SMem* sm, double td, float ta, float tb,
                                int sid, unsigned bg,
                                double& exd, float& exa, float& exb) {
    const int lane = threadIdx.x & 31, wid = threadIdx.x >> 5;
    const int buf = sid & 1;
    __syncthreads();
    double wd = warp_iscan_d(td, lane);
    float wa = warp_iscan_f(ta, lane);
    float wb = warp_iscan_f(tb, lane);
    if (lane == 31) { sm->wd[wid] = wd; sm->wf[wid] = wa; sm->wf2[wid] = wb; }
    __syncthreads();
    if (wid == 0) {
        double vd = sm->wd[lane];
        float va = sm->wf[lane];
        float vb = sm->wf2[lane];
        double sd = warp_iscan_d(vd, lane);
        float sa = warp_iscan_f(va, lane);
        float sb = warp_iscan_f(vb, lane);
        sm->wd[lane] = sd - vd;
        sm->wf[lane] = sa - va;
        sm->wf2[lane] = sb - vb;
        if (lane == 31) {
            g_totd[buf][blockIdx.x] = sd;
            g_totf[buf][blockIdx.x] = sa;
            g_totf2[buf][blockIdx.x] = sb;
        }
    }
    grid_barrier(bg + (unsigned)sid + 1u);
    if (wid == 0) {
        double ad = 0.0; float aa = 0.f, ab = 0.f;
#pragma unroll
        for (int j = lane; j < GRD; j += 32)
            if (j < (int)blockIdx.x) {
                ad += g_totd[buf][j];
                aa += g_totf[buf][j];
                ab += g_totf2[buf][j];
            }
        ad = warp_sum_d(ad); aa = warp_sum_f(aa); ab = warp_sum_f(ab);
        if (lane == 0) { sm->bd = ad; sm->bf = aa; sm->bf2 = ab; }
    }
    __syncthreads();
    exd = sm->bd + sm->wd[wid] + (wd - td);
    exa = sm->bf + sm->wf[wid] + (wa - ta);
    exb = sm->bf2 + sm->wf2[wid] + (wb - tb);
}

// f32-replicated field: psi = fl32(ku*z); 2-term Cody-Waite; fast cos.
static __device__ __forceinline__ float fval32(float kuf, float zf) {
    float psi = __fmul_rn(kuf, zf);
    float n = rintf(psi * 0.15915494309189535f);
    float r = fmaf(-n, 6.28125f, psi);
    r = fmaf(-n, 1.9353071795864769e-3f, r);
    return __cosf(r);
}
// sin(ku*z) for the analytic init (accuracy, not replication).
static __device__ __forceinline__ float sval32(float kuf, float zf) {
    float psi = __fmul_rn(kuf, zf);
    float n = rintf(psi * 0.15915494309189535f);
    float r = fmaf(-n, 6.28125f, psi);
    r = fmaf(-n, 1.9353071795864769e-3f, r);
    return __sinf(r);
}

// fl32(ref + c) - ref modeled as ulp(ref)-grid rounding of c (all f32).
static __device__ __forceinline__ float qstepf(float c, float ref) {
    int e = (int)((__float_as_uint(fabsf(ref)) >> 23) & 0xffu);
    if (e < 24) return c;
    float u  = __uint_as_float((unsigned)(e - 23) << 23);   // 2^(e-150)
    float iu = __uint_as_float((unsigned)(277 - e) << 23);  // 2^(150-e)
    return u * rintf(c * iu);
}

__global__ void __launch_bounds__(TPB, 1) picard_all(
    const float* __restrict__ time, const float* __restrict__ r0v,
    const float* __restrict__ d0v, const float* __restrict__ gptr,
    const float* __restrict__ b0ptr, const float* __restrict__ kuptr,
    float* __restrict__ out, int N)
{
    __shared__ SMem sm;
    const int tid = threadIdx.x;

    // ---- preamble: once per CTA (f64 transcendentals) ----
    if (tid == 0) {
        sm.base = g_gen;
        const double dt = (double)(time[1] - time[0]);
        const double gamma = (double)gptr[0];
        const double B0 = (double)b0ptr[0];
        const float kuf = kuptr[0];
        float dxf = d0v[0], dyf = d0v[1], dzf = d0v[2];
        float gf = gptr[0];
        float dnf = sqrtf(dxf * dxf + dyf * dyf + dzf * dzf);
        float csf = 0.29979245f * sqrtf(gf * gf - 1.0f);
        const double px0 = (double)(csf * dxf / dnf);
        const double py0 = (double)(csf * dyf / dnf);
        const double pz0 = (double)(csf * dzf / dnf);
        const double x0 = (double)r0v[0], y0 = (double)r0v[1], z0 = (double)r0v[2];
        const double invg = 1.0 / gamma;
        const double Pmag = sqrt(px0 * px0 + pz0 * pz0);
        const double phi0 = atan2(px0, pz0);
        const double cy = dt * py0 * invg;
        const double ku_d = (double)kuf;
        const double psi0 = ku_d * z0;
        // secular-corrected ballistic mean velocities
        const double vz0d = pz0 * invg;
        const double a0 = B0 * invg / (ku_d * vz0d);
        const double bph = phi0 - a0 * sin(psi0);
        const double a2 = a0 * a0;
        const double j0a = 1.0 - 0.25 * a2 + a2 * a2 / 64.0;
        const double vzm = Pmag * invg * cos(bph) * j0a;
        const double vzmdt = vzm * dt;
        const double aamp = B0 * invg / (ku_d * vzm);   // analytic theta amplitude
        const double vxm = Pmag * invg * sin(bph) * j0a;
        const double Cosc = Pmag * invg * cos(bph) * aamp / (ku_d * vzm);

        sm.c.kuf = kuf;
        sm.c.Kthf = (float)(B0 * dt * invg);
        sm.c.Kzf  = (float)(dt * invg * Pmag);
        sm.c.phi0f = (float)phi0;
        sm.c.f0f = fval32(kuf, (float)z0);
        sm.c.cyf = (float)cy;
        sm.c.y0f = (float)y0;
        sm.c.x0f = (float)x0;
        sm.c.scalef = (float)(Pmag / (0.29979245 * gamma));
        sm.c.byc    = (float)(py0 / (0.29979245 * gamma));
        sm.c.vzmdtf = (float)vzmdt;
        sm.c.aampf  = (float)aamp;
        sm.c.spsi0f = (float)sin(psi0);
        sm.c.vxmdtf = (float)(vxm * dt);
        sm.c.Coscf  = (float)Cosc;
        sm.c.z0 = z0; sm.c.vzmdt = vzmdt; sm.c.x0 = x0; sm.c.y0 = y0;
    }
    __syncthreads();

    const unsigned bg = sm.base;
    const float kuf = sm.c.kuf, Kthf = sm.c.Kthf, Kzf = sm.c.Kzf;
    const float phi0f = sm.c.phi0f, f0f = sm.c.f0f, cyf = sm.c.cyf;
    const float y0f = sm.c.y0f, x0f = sm.c.x0f;
    const float scalef = sm.c.scalef, byc = sm.c.byc, vzmdtf = sm.c.vzmdtf;
    const float aampf = sm.c.aampf, spsi0f = sm.c.spsi0f;
    const float vxmdtf = sm.c.vxmdtf, Coscf = sm.c.Coscf;
    const double z0 = sm.c.z0;

    const int base = ((int)blockIdx.x * TPB + tid) * EPT;
    const int blk0 = (int)blockIdx.x * TILE;

    float zf[EPT], fs[EPT], qs[EPT], cxs[EPT];
    int sid = 0;

    // ---- init: analytic Picard-1 (no f-scan; 1 q-scan) ----
    {
        double zb = z0 + sm.c.vzmdt * (double)base;
        float zbhi = (float)zb;
        float zblo = (float)(zb - (double)zbhi);
        float Tq = 0.f;
#pragma unroll
        for (int k = 0; k < EPT; ++k) {
            int i = base + k;
            float zball = zbhi + (zblo + (float)k * vzmdtf);
            float zmid  = zbhi + (zblo + ((float)k + 0.5f) * vzmdtf);
            float th = aampf * (sval32(kuf, zmid) - spsi0f);
            float u = phi0f + th;
            float u2 = u * u;
            float cu = fmaf(u2, fmaf(u2, 1.f / 24.f, -0.5f), 1.f);
            float qf = (i < N) ? qstepf(Kzf * cu, zball) : 0.f;
            qs[k] = qf;
            Tq += qf;                          // exact (grid multiples)
        }
        double exq = scan_d(&sm, (double)Tq, sid, bg); sid++;

        double basez = z0 + exq;
        float bzhi = (float)basez;
        float bzlo = (float)(basez - (double)bzhi);
        float runq = 0.f;
#pragma unroll
        for (int k = 0; k < EPT; ++k) {
            zf[k] = bzhi + (bzlo + runq);
            runq += qs[k];                     // exact f32 chain
        }
    }

    // ---- final sweep: field scan ----
    float Tf = 0.f;
#pragma unroll
    for (int k = 0; k < EPT; ++k) {
        int i = base + k;
        float f = (i < N) ? fval32(kuf, zf[k]) : 0.f;
        fs[k] = f; Tf += f;
    }
    float exf = scan_f(&sm, Tf, sid, bg); sid++;

    // ---- theta + all three quantized increments (pointwise binade refs) ----
    float Tq = 0.f, Tqx = 0.f, Tqy = 0.f;
    {
        float run = exf;
#pragma unroll
        for (int k = 0; k < EPT; ++k) {
            int i = base + k;
            float f = fs[k];
            run += f;
            float th  = Kthf * (run - 0.5f * (f0f + f));
            float thm = fmaf(0.5f * Kthf, f, th);
            float u = phi0f + thm;
            float u2 = u * u;
            float cu = fmaf(u2, fmaf(u2, 1.f / 24.f, -0.5f), 1.f);
            float su = u * fmaf(u2, fmaf(u2, 1.f / 120.f, -1.f / 6.f), 1.f);
            float qf = (i < N) ? qstepf(Kzf * cu, zf[k]) : 0.f;
            qs[k] = qf;   Tq += qf;
            // analytic plain-x binade reference
            float cx = Kzf * su;
            float xpl = fmaf(vxmdtf, (float)i, x0f) + Coscf * (f0f - f);
            float qx = (i < N) ? qstepf(cx, xpl) : 0.f;
            cxs[k] = qx;  Tqx += qx;
            // closed-form plain-y binade reference
            float ypl = fmaf(cyf, (float)i, y0f);
            float qy = (i < N) ? qstepf(cyf, ypl) : 0.f;
            Tqy += qy;
            fs[k] = th;                        // keep node theta
        }
    }
    double exq; float exqx, exqy;
    scan_dff(&sm, (double)Tq, Tqx, Tqy, sid, bg, exq, exqx, exqy); sid++;

    // ---- z ladder ----
    {
        double basez = z0 + exq;
        float bzhi = (float)basez;
        float bzlo = (float)(basez - (double)bzhi);
        float runq = 0.f;
#pragma unroll
        for (int k = 0; k < EPT; ++k) {
            zf[k] = bzhi + (bzlo + runq);
            runq += qs[k];
        }
    }

    // ---- outputs (smem transpose, coalesced float4) ----
    const size_t Ns = (size_t)N;
    const int nrem = N - blk0;
    const bool full = (nrem >= TILE) && ((Ns & 3u) == 0) && ((blk0 & 3) == 0);

    // pass 1: x (stage 0), y (stage 1) — qy recomputed pointwise
    {
        double basex = sm.c.x0 + (double)exqx;
        float bxhi = (float)basex;
        float bxlo = (float)(basex - (double)bxhi);
        double basey = sm.c.y0 + (double)exqy;
        float byhi = (float)basey;
        float bylo = (float)(basey - (double)byhi);
        float runqx = 0.f, runqy = 0.f;
        __syncthreads();
#pragma unroll
        for (int k = 0; k < EPT; ++k) {
            sm.stage[0][tid * EPT + k] = bxhi + (bxlo + runqx);
            sm.stage[1][tid * EPT + k] = byhi + (bylo + runqy);
            runqx += cxs[k];
            float ypl = fmaf(cyf, (float)(base + k), y0f);
            runqy += qstepf(cyf, ypl);
        }
        __syncthreads();
        if (full) {
            const float4* s0 = (const float4*)sm.stage[0];
            const float4* s1 = (const float4*)sm.stage[1];
            float4* o0 = (float4*)(out + blk0);
            float4* o1 = (float4*)(out + Ns + blk0);
            for (int j = tid; j < TILE / 4; j += TPB) { o0[j] = s0[j]; o1[j] = s1[j]; }
        } else {
            for (int j = tid; j < TILE; j += TPB)
                if (j < nrem) { out[blk0 + j] = sm.stage[0][j]; out[Ns + blk0 + j] = sm.stage[1][j]; }
        }
    }
    // pass 2: z (stage 0), beta_y constant direct
    {
        __syncthreads();
#pragma unroll
        for (int k = 0; k < EPT; ++k)
            sm.stage[0][tid * EPT + k] = zf[k];
        __syncthreads();
        if (full) {
            const float4* s0 = (const float4*)sm.stage[0];
            float4* o0 = (float4*)(out + 2 * Ns + blk0);
            float4* o1 = (float4*)(out + 4 * Ns + blk0);
            float4 cv = make_float4(byc, byc, byc, byc);
            for (int j = tid; j < TILE / 4; j += TPB) { o0[j] = s0[j]; o1[j] = cv; }
        } else {
            for (int j = tid; j < TILE; j += TPB)
                if (j < nrem) { out[2 * Ns + blk0 + j] = sm.stage[0][j]; out[4 * Ns + blk0 + j] = byc; }
        }
    }
    // pass 3: beta_x (stage 0), beta_z (stage 1) — share u-poly
    {
        __syncthreads();
#pragma unroll
        for (int k = 0; k < EPT; ++k) {
            float u = phi0f + fs[k];
            float u2 = u * u;
            float su = u * fmaf(u2, fmaf(u2, 1.f / 120.f, -1.f / 6.f), 1.f);
            float cu = fmaf(u2, fmaf(u2, 1.f / 24.f, -0.5f), 1.f);
            sm.stage[0][tid * EPT + k] = scalef * su;
            sm.stage[1][tid * EPT + k] = scalef * cu;
        }
        __syncthreads();
        if (full) {
            const float4* s0 = (const float4*)sm.stage[0];
            const float4* s1 = (const float4*)sm.stage[1];
            float4* o0 = (float4*)(out + 3 * Ns + blk0);
            float4* o1 = (float4*)(out + 5 * Ns + blk0);
            for (int j = tid; j < TILE / 4; j += TPB) { o0[j] = s0[j]; o1[j] = s1[j]; }
        } else {
            for (int j = tid; j < TILE; j += TPB)
                if (j < nrem) { out[3 * Ns + blk0 + j] = sm.stage[0][j]; out[5 * Ns + blk0 + j] = sm.stage[1][j]; }
        }
    }
}

// ---------------- serial fallback (N exceeds capacity) ---------------------
__global__ void __launch_bounds__(32, 1) track_seq_kernel(
    const float* __restrict__ time, const float* __restrict__ r0v,
    const float* __restrict__ d0v, const float* __restrict__ gptr,
    const float* __restrict__ b0ptr, const float* __restrict__ kuptr,
    float* __restrict__ out, int N)
{
    if (threadIdx.x != 0 || blockIdx.x != 0) return;
    const float C = 0.29979245f;
    const float dt = time[1] - time[0];
    const float dt2 = 0.5f * dt, h6 = dt * (1.0f / 6.0f);
    const float gamma = gptr[0], B0 = b0ptr[0], ku = kuptr[0];
    const float A = 1.0f / gamma;
    const float KdtA2 = ku * dt2 * A, KdtA = ku * dt * A;
    const float inv_cg = 1.0f / (C * gamma);
    float dx0 = d0v[0], dy0 = d0v[1], dz0 = d0v[2];
    float dn = sqrtf(dx0 * dx0 + dy0 * dy0 + dz0 * dz0);
    float pscale = C * sqrtf(gamma * gamma - 1.0f) / dn;
    float px = pscale * dx0, py = pscale * dy0, pz = pscale * dz0;
    float x = r0v[0], y = r0v[1], z = r0v[2];
    const float vy = py * A;
    float cps = cosf(ku * z), sps = sinf(ku * z);
    float Bc = B0 * cps, Bs = B0 * sps;
    const size_t Ns = (size_t)N;
    out[0] = x; out[Ns] = y; out[2 * Ns] = z;
    out[3 * Ns] = px * inv_cg; out[4 * Ns] = py * inv_cg; out[5 * Ns] = pz * inv_cg;
#pragma unroll 1
    for (int i = 1; i < N; ++i) {
        float vx1 = px * A, vz1 = pz * A;
        float apx1 = pz * Bc * A, apz1 = -px * Bc * A;
        float px2 = fmaf(apx1, dt2, px), pz2 = fmaf(apz1, dt2, pz);
        float d2 = KdtA2 * pz, q2 = d2 * d2;
        float sd2 = d2 * fmaf(-0.16666667f, q2, 1.0f), cd2 = fmaf(-0.5f, q2, 1.0f);
        float By2 = fmaf(Bc, cd2, -Bs * sd2);
        float vx2 = px2 * A, vz2 = pz2 * A;
        float apx2 = pz2 * By2 * A, apz2 = -px2 * By2 * A;
        float px3 = fmaf(apx2, dt2, px), pz3 = fmaf(apz2, dt2, pz);
        float d3 = KdtA2 * pz2, q3 = d3 * d3;
        float sd3 = d3 * fmaf(-0.16666667f, q3, 1.0f), cd3 = fmaf(-0.5f, q3, 1.0f);
        float By3 = fmaf(Bc, cd3, -Bs * sd3);
        float vx3 = px3 * A, vz3 = pz3 * A;
        float apx3 = pz3 * By3 * A, apz3 = -px3 * By3 * A;
        float px4 = fmaf(apx3, dt, px), pz4 = fmaf(apz3, dt, pz);
        float d4 = KdtA * pz3, q4 = d4 * d4;
        float sd4 = d4 * fmaf(-0.16666667f, q4, 1.0f), cd4 = fmaf(-0.5f, q4, 1.0f);
        float By4 = fmaf(Bc, cd4, -Bs * sd4);
        float vx4 = px4 * A, vz4 = pz4 * A;
        float apx4 = pz4 * By4 * A, apz4 = -px4 * By4 * A;
        float dxs = h6 * (vx1 + 2.0f * (vx2 + vx3) + vx4);
        float dzs = h6 * (vz1 + 2.0f * (vz2 + vz3) + vz4);
        px = px + h6 * (apx1 + 2.0f * (apx2 + apx3) + apx4);
        pz = pz + h6 * (apz1 + 2.0f * (apz2 + apz3) + apz4);
        x += dxs; y += dt * vy; z += dzs;
        float dp = ku * dzs, qp = dp * dp;
        float sdp = dp * fmaf(-0.16666667f, qp, 1.0f), cdp = fmaf(-0.5f, qp, 1.0f);
        float cn = fmaf(cps, cdp, -sps * sdp);
        float sn = fmaf(sps, cdp, cps * sdp);
        float nr = fmaf(cn, cn, sn * sn);
        float corr = fmaf(-0.5f, nr, 1.5f);
        cps = cn * corr; sps = sn * corr;
        Bc = B0 * cps; Bs = B0 * sps;
        out[i] = x; out[Ns + i] = y; out[2 * Ns + i] = z;
        out[3 * Ns + i] = px * inv_cg; out[4 * Ns + i] = py * inv_cg; out[5 * Ns + i] = pz * inv_cg;
    }
}

extern "C" void kernel_launch(void* const* d_in, const int* in_sizes, int n_in,
                              void* d_out, int out_size) {
    const float* time = (const float*)d_in[0];
    const float* r0   = (const float*)d_in[1];
    const float* d0   = (const float*)d_in[2];
    const float* gam  = (const float*)d_in[3];
    const float* B0   = (const float*)d_in[4];
    const float* ku   = (const float*)d_in[5];
    float* out = (float*)d_out;
    int N = in_sizes[0];

    if (N > CAP) {
        track_seq_kernel<<<1, 32>>>(time, r0, d0, gam, B0, ku, out, N);
        return;
    }
    picard_all<<<GRD, TPB>>>(time, r0, d0, gam, B0, ku, out, N);
}

// round 14
// speedup vs baseline: 1.1581x; 1.1581x over previous
#include <cuda_runtime.h>
#include <cuda_bf16.h>

// Persistent single-launch parallel-in-time undulator tracker.
// Numerics identical to the 43.7us R12 kernel (analytic Picard-1 init +
// final quantized-replication sweep, 4 scans). Sync rewritten: NO global
// barriers — each scan publishes a (total, generation-flag) pair and block b
// waits only on predecessors j<b (exclusive prefix needs nothing else).
// Generations are self-synchronized: every launch bumps every flag once.

#define TPB 1024
#define GRD 148
#define EPT 7
#define TILE (TPB * EPT)          // 7168
#define CAP (TILE * GRD)          // 1,060,864

__device__ volatile int    g_flg[4][GRD];   // zero-init; +1 per launch per chain
__device__ volatile float  g_tf[4][GRD];
__device__ volatile double g_td[2][GRD];

struct SCon {
    float kuf, Kthf, Kzf, phi0f, f0f, cyf, y0f, x0f, scalef, byc, vzmdtf;
    float aampf, spsi0f;
    double z0, vzmdt, x0, y0;
    int expgen;
};

struct SMem {
    __align__(16) float stage[2][TILE];   // 56 KB output transpose buffers
    SCon c;
    float  wf[32], wf2[32];
    double wd[32];
    float  bf, bf2;
    double bd;
};

static __device__ __forceinline__ float warp_iscan_f(float v, int lane) {
#pragma unroll
    for (int d = 1; d < 32; d <<= 1) {
        float n = __shfl_up_sync(0xffffffffu, v, d);
        if (lane >= d) v += n;
    }
    return v;
}
static __device__ __forceinline__ double warp_iscan_d(double v, int lane) {
#pragma unroll
    for (int d = 1; d < 32; d <<= 1) {
        double n = __shfl_up_sync(0xffffffffu, v, d);
        if (lane >= d) v += n;
    }
    return v;
}
static __device__ __forceinline__ float warp_sum_f(float v) {
#pragma unroll
    for (int d = 16; d; d >>= 1) v += __shfl_down_sync(0xffffffffu, v, d);
    return v;
}
static __device__ __forceinline__ double warp_sum_d(double v) {
#pragma unroll
    for (int d = 16; d; d >>= 1) v += __shfl_down_sync(0xffffffffu, v, d);
    return v;
}

// Wait (warp 0 collective) until all predecessor blocks published chain c.
static __device__ __forceinline__ void wait_pred(int c, int b, int lane, int exp) {
    for (int j = lane; j < b; j += 32)
        while (g_flg[c][j] != exp) { }
    __threadfence();
}

// ---- scans: block-local reduce -> publish -> predecessor-wait -> prefix ----
static __device__ float scan_f(SMem* sm, float tf, int cF, int cFlag) {
    const int lane = threadIdx.x & 31, wid = threadIdx.x >> 5;
    const int b = (int)blockIdx.x;
    const int exp = sm->c.expgen;
    __syncthreads();
    float wf = warp_iscan_f(tf, lane);
    if (lane == 31) sm->wf[wid] = wf;
    __syncthreads();
    if (wid == 0) {
        float vf = sm->wf[lane];
        float sf = warp_iscan_f(vf, lane);
        sm->wf[lane] = sf - vf;
        if (lane == 31) g_tf[cF][b] = sf;
        __threadfence();
        if (lane == 31) g_flg[cFlag][b] = exp;
        wait_pred(cFlag, b, lane, exp);
        float af = 0.f;
        for (int j = lane; j < b; j += 32) af += g_tf[cF][j];
        af = warp_sum_f(af);
        if (lane == 0) sm->bf = af;
    }
    __syncthreads();
    return sm->bf + sm->wf[wid] + (wf - tf);
}

static __device__ double scan_d(SMem* sm, double td, int cD, int cFlag) {
    const int lane = threadIdx.x & 31, wid = threadIdx.x >> 5;
    const int b = (int)blockIdx.x;
    const int exp = sm->c.expgen;
    __syncthreads();
    double wd = warp_iscan_d(td, lane);
    if (lane == 31) sm->wd[wid] = wd;
    __syncthreads();
    if (wid == 0) {
        double vd = sm->wd[lane];
        double sd = warp_iscan_d(vd, lane);
        sm->wd[lane] = sd - vd;
        if (lane == 31) g_td[cD][b] = sd;
        __threadfence();
        if (lane == 31) g_flg[cFlag][b] = exp;
        wait_pred(cFlag, b, lane, exp);
        double ad = 0.0;
        for (int j = lane; j < b; j += 32) ad += g_td[cD][j];
        ad = warp_sum_d(ad);
        if (lane == 0) sm->bd = ad;
    }
    __syncthreads();
    return sm->bd + sm->wd[wid] + (wd - td);
}

static __device__ void scan_fd(SMem* sm, float tf, double td, int cF, int cD,
                               int cFlag, float& exf, double& exd) {
    const int lane = threadIdx.x & 31, wid = threadIdx.x >> 5;
    const int b = (int)blockIdx.x;
    const int exp = sm->c.expgen;
    __syncthreads();
    float wf = warp_iscan_f(tf, lane);
    double wd = warp_iscan_d(td, lane);
    if (lane == 31) { sm->wf[wid] = wf; sm->wd[wid] = wd; }
    __syncthreads();
    if (wid == 0) {
        float vf = sm->wf[lane];
        double vd = sm->wd[lane];
        float sf = warp_iscan_f(vf, lane);
        double sd = warp_iscan_d(vd, lane);
        sm->wf[lane] = sf - vf;
        sm->wd[lane] = sd - vd;
        if (lane == 31) { g_tf[cF][b] = sf; g_td[cD][b] = sd; }
        __threadfence();
        if (lane == 31) g_flg[cFlag][b] = exp;
        wait_pred(cFlag, b, lane, exp);
        float af = 0.f; double ad = 0.0;
        for (int j = lane; j < b; j += 32) { af += g_tf[cF][j]; ad += g_td[cD][j]; }
        af = warp_sum_f(af); ad = warp_sum_d(ad);
        if (lane == 0) { sm->bf = af; sm->bd = ad; }
    }
    __syncthreads();
    exf = sm->bf + sm->wf[wid] + (wf - tf);
    exd = sm->bd + sm->wd[wid] + (wd - td);
}

static __device__ void scan_ff(SMem* sm, float ta, float tb, int cF, int cF2,
                               int cFlag, float& exa, float& exb) {
    const int lane = threadIdx.x & 31, wid = threadIdx.x >> 5;
    const int b = (int)blockIdx.x;
    const int exp = sm->c.expgen;
    __syncthreads();
    float wa = warp_iscan_f(ta, lane);
    float wb = warp_iscan_f(tb, lane);
    if (lane == 31) { sm->wf[wid] = wa; sm->wf2[wid] = wb; }
    __syncthreads();
    if (wid == 0) {
        float va = sm->wf[lane];
        float vb = sm->wf2[lane];
        float sa = warp_iscan_f(va, lane);
        float sb = warp_iscan_f(vb, lane);
        sm->wf[lane] = sa - va;
        sm->wf2[lane] = sb - vb;
        if (lane == 31) { g_tf[cF][b] = sa; g_tf[cF2][b] = sb; }
        __threadfence();
        if (lane == 31) g_flg[cFlag][b] = exp;
        wait_pred(cFlag, b, lane, exp);
        float aa = 0.f, ab = 0.f;
        for (int j = lane; j < b; j += 32) { aa += g_tf[cF][j]; ab += g_tf[cF2][j]; }
        aa = warp_sum_f(aa); ab = warp_sum_f(ab);
        if (lane == 0) { sm->bf = aa; sm->bf2 = ab; }
    }
    __syncthreads();
    exa = sm->bf + sm->wf[wid] + (wa - ta);
    exb = sm->bf2 + sm->wf2[wid] + (wb - tb);
}

// f32-replicated field: psi = fl32(ku*z); 2-term Cody-Waite; fast cos.
static __device__ __forceinline__ float fval32(float kuf, float zf) {
    float psi = __fmul_rn(kuf, zf);
    float n = rintf(psi * 0.15915494309189535f);
    float r = fmaf(-n, 6.28125f, psi);
    r = fmaf(-n, 1.9353071795864769e-3f, r);
    return __cosf(r);
}
// sin(ku*z) for the analytic init (accuracy, not replication).
static __device__ __forceinline__ float sval32(float kuf, float zf) {
    float psi = __fmul_rn(kuf, zf);
    float n = rintf(psi * 0.15915494309189535f);
    float r = fmaf(-n, 6.28125f, psi);
    r = fmaf(-n, 1.9353071795864769e-3f, r);
    return __sinf(r);
}

// fl32(ref + c) - ref modeled as ulp(ref)-grid rounding of c (all f32).
static __device__ __forceinline__ float qstepf(float c, float ref) {
    int e = (int)((__float_as_uint(fabsf(ref)) >> 23) & 0xffu);
    if (e < 24) return c;
    float u  = __uint_as_float((unsigned)(e - 23) << 23);   // 2^(e-150)
    float iu = __uint_as_float((unsigned)(277 - e) << 23);  // 2^(150-e)
    return u * rintf(c * iu);
}

__global__ void __launch_bounds__(TPB, 1) picard_all(
    const float* __restrict__ time, const float* __restrict__ r0v,
    const float* __restrict__ d0v, const float* __restrict__ gptr,
    const float* __restrict__ b0ptr, const float* __restrict__ kuptr,
    float* __restrict__ out, int N)
{
    __shared__ SMem sm;
    const int tid = threadIdx.x;

    // ---- preamble: once per CTA (f64 transcendentals) ----
    if (tid == 0) {
        sm.c.expgen = g_flg[0][blockIdx.x] + 1;   // self-synchronized generation
        const double dt = (double)(time[1] - time[0]);
        const double gamma = (double)gptr[0];
        const double B0 = (double)b0ptr[0];
        const float kuf = kuptr[0];
        float dxf = d0v[0], dyf = d0v[1], dzf = d0v[2];
        float gf = gptr[0];
        float dnf = sqrtf(dxf * dxf + dyf * dyf + dzf * dzf);
        float csf = 0.29979245f * sqrtf(gf * gf - 1.0f);
        const double px0 = (double)(csf * dxf / dnf);
        const double py0 = (double)(csf * dyf / dnf);
        const double pz0 = (double)(csf * dzf / dnf);
        const double x0 = (double)r0v[0], y0 = (double)r0v[1], z0 = (double)r0v[2];
        const double invg = 1.0 / gamma;
        const double Pmag = sqrt(px0 * px0 + pz0 * pz0);
        const double phi0 = atan2(px0, pz0);
        const double cy = dt * py0 * invg;
        const double ku_d = (double)kuf;
        const double psi0 = ku_d * z0;
        // secular-corrected ballistic mean velocity
        const double vz0d = pz0 * invg;
        const double a0 = B0 * invg / (ku_d * vz0d);
        const double bph = phi0 - a0 * sin(psi0);
        const double a2 = a0 * a0;
        const double j0a = 1.0 - 0.25 * a2 + a2 * a2 / 64.0;
        const double vzm = Pmag * invg * cos(bph) * j0a;
        const double vzmdt = vzm * dt;
        const double aamp = B0 * invg / (ku_d * vzm);   // analytic theta amplitude

        sm.c.kuf = kuf;
        sm.c.Kthf = (float)(B0 * dt * invg);
        sm.c.Kzf  = (float)(dt * invg * Pmag);
        sm.c.phi0f = (float)phi0;
        sm.c.f0f = fval32(kuf, (float)z0);
        sm.c.cyf = (float)cy;
        sm.c.y0f = (float)y0;
        sm.c.x0f = (float)x0;
        sm.c.scalef = (float)(Pmag / (0.29979245 * gamma));
        sm.c.byc    = (float)(py0 / (0.29979245 * gamma));
        sm.c.vzmdtf = (float)vzmdt;
        sm.c.aampf  = (float)aamp;
        sm.c.spsi0f = (float)sin(psi0);
        sm.c.z0 = z0; sm.c.vzmdt = vzmdt; sm.c.x0 = x0; sm.c.y0 = y0;
    }
    __syncthreads();

    const float kuf = sm.c.kuf, Kthf = sm.c.Kthf, Kzf = sm.c.Kzf;
    const float phi0f = sm.c.phi0f, f0f = sm.c.f0f, cyf = sm.c.cyf;
    const float y0f = sm.c.y0f, x0f = sm.c.x0f;
    const float scalef = sm.c.scalef, byc = sm.c.byc, vzmdtf = sm.c.vzmdtf;
    const float aampf = sm.c.aampf, spsi0f = sm.c.spsi0f;
    const double z0 = sm.c.z0;

    const int base = ((int)blockIdx.x * TPB + tid) * EPT;
    const int blk0 = (int)blockIdx.x * TILE;

    float zf[EPT], fs[EPT], qs[EPT], cxs[EPT];

    // ---- init: analytic Picard-1 (no f-scan; 1 q-scan) ----
    {
        double zb = z0 + sm.c.vzmdt * (double)base;
        float zbhi = (float)zb;
        float zblo = (float)(zb - (double)zbhi);
        float Tq = 0.f;
#pragma unroll
        for (int k = 0; k < EPT; ++k) {
            int i = base + k;
            float zball = zbhi + (zblo + (float)k * vzmdtf);
            float zmid  = zbhi + (zblo + ((float)k + 0.5f) * vzmdtf);
            float th = aampf * (sval32(kuf, zmid) - spsi0f);
            float u = phi0f + th;
            float u2 = u * u;
            float cu = fmaf(u2, fmaf(u2, 1.f / 24.f, -0.5f), 1.f);
            float qf = (i < N) ? qstepf(Kzf * cu, zball) : 0.f;
            qs[k] = qf;
            Tq += qf;                          // exact (grid multiples)
        }
        double exq = scan_d(&sm, (double)Tq, 0, 0);

        double basez = z0 + exq;
        float bzhi = (float)basez;
        float bzlo = (float)(basez - (double)bzhi);
        float runq = 0.f;
#pragma unroll
        for (int k = 0; k < EPT; ++k) {
            zf[k] = bzhi + (bzlo + runq);
            runq += qs[k];                     // exact f32 chain
        }
    }

    // ---- final sweep: field scan ----
    float Tf = 0.f;
#pragma unroll
    for (int k = 0; k < EPT; ++k) {
        int i = base + k;
        float f = (i < N) ? fval32(kuf, zf[k]) : 0.f;
        fs[k] = f; Tf += f;
    }
    float exf = scan_f(&sm, Tf, 0, 1);

    float Tq = 0.f, Tcx = 0.f; float run = exf;
#pragma unroll
    for (int k = 0; k < EPT; ++k) {
        int i = base + k;
        float f = fs[k];
        run += f;
        float th  = Kthf * (run - 0.5f * (f0f + f));
        float thm = fmaf(0.5f * Kthf, f, th);
        float u = phi0f + thm;
        float u2 = u * u;
        float cu = fmaf(u2, fmaf(u2, 1.f / 24.f, -0.5f), 1.f);
        float su = u * fmaf(u2, fmaf(u2, 1.f / 120.f, -1.f / 6.f), 1.f);
        float qf = (i < N) ? qstepf(Kzf * cu, zf[k]) : 0.f;
        float cx = (i < N) ? Kzf * su : 0.f;
        qs[k] = qf;   Tq += qf;
        cxs[k] = cx;  Tcx += cx;
        fs[k] = th;                            // keep node theta
    }
    float excx; double exq;
    scan_fd(&sm, Tcx, (double)Tq, 1, 1, 2, excx, exq);

    float Tqx = 0.f, Tqy = 0.f;
    {
        double basez = z0 + exq;
        float bzhi = (float)basez;
        float bzlo = (float)(basez - (double)bzhi);
        float runq = 0.f, runcx = excx;
#pragma unroll
        for (int k = 0; k < EPT; ++k) {
            int i = base + k;
            zf[k] = bzhi + (bzlo + runq);
            runq += qs[k];
            float xpl = x0f + runcx;                 // plain x (binade ref)
            runcx += cxs[k];
            float qx = (i < N) ? qstepf(cxs[k], xpl) : 0.f;
            cxs[k] = qx;  Tqx += qx;
            float ypl = fmaf(cyf, (float)i, y0f);    // plain y (binade ref)
            float qy = (i < N) ? qstepf(cyf, ypl) : 0.f;
            qs[k] = qy;   Tqy += qy;
        }
    }
    float exqx, exqy;
    scan_ff(&sm, Tqx, Tqy, 2, 3, 3, exqx, exqy);

    // ---- outputs (smem transpose, coalesced float4) ----
    const size_t Ns = (size_t)N;
    const int nrem = N - blk0;
    const bool full = (nrem >= TILE) && ((Ns & 3u) == 0) && ((blk0 & 3) == 0);

    // pass 1: x (stage 0), y (stage 1)
    {
        double basex = sm.c.x0 + (double)exqx;
        float bxhi = (float)basex;
        float bxlo = (float)(basex - (double)bxhi);
        double basey = sm.c.y0 + (double)exqy;
        float byhi = (float)basey;
        float bylo = (float)(basey - (double)byhi);
        float runqx = 0.f, runqy = 0.f;
        __syncthreads();
#pragma unroll
        for (int k = 0; k < EPT; ++k) {
            sm.stage[0][tid * EPT + k] = bxhi + (bxlo + runqx);
            sm.stage[1][tid * EPT + k] = byhi + (bylo + runqy);
            runqx += cxs[k];
            runqy += qs[k];
        }
        __syncthreads();
        if (full) {
            const float4* s0 = (const float4*)sm.stage[0];
            const float4* s1 = (const float4*)sm.stage[1];
            float4* o0 = (float4*)(out + blk0);
            float4* o1 = (float4*)(out + Ns + blk0);
            for (int j = tid; j < TILE / 4; j += TPB) { o0[j] = s0[j]; o1[j] = s1[j]; }
        } else {
            for (int j = tid; j < TILE; j += TPB)
                if (j < nrem) { out[blk0 + j] = sm.stage[0][j]; out[Ns + blk0 + j] = sm.stage[1][j]; }
        }
    }
    // pass 2: z (stage 0), beta_y constant direct
    {
        __syncthreads();
#pragma unroll
        for (int k = 0; k < EPT; ++k)
            sm.stage[0][tid * EPT + k] = zf[k];
        __syncthreads();
        if (full) {
            const float4* s0 = (const float4*)sm.stage[0];
            float4* o0 = (float4*)(out + 2 * Ns + blk0);
            float4* o1 = (float4*)(out + 4 * Ns + blk0);
            float4 cv = make_float4(byc, byc, byc, byc);
            for (int j = tid; j < TILE / 4; j += TPB) { o0[j] = s0[j]; o1[j] = cv; }
        } else {
            for (int j = tid; j < TILE; j += TPB)
                if (j < nrem) { out[2 * Ns + blk0 + j] = sm.stage[0][j]; out[4 * Ns + blk0 + j] = byc; }
        }
    }
    // pass 3: beta_x (stage 0), beta_z (stage 1) — share u-poly
    {
        __syncthreads();
#pragma unroll
        for (int k = 0; k < EPT; ++k) {
            float u = phi0f + fs[k];
            float u2 = u * u;
            float su = u * fmaf(u2, fmaf(u2, 1.f / 120.f, -1.f / 6.f), 1.f);
            float cu = fmaf(u2, fmaf(u2, 1.f / 24.f, -0.5f), 1.f);
            sm.stage[0][tid * EPT + k] = scalef * su;
            sm.stage[1][tid * EPT + k] = scalef * cu;
        }
        __syncthreads();
        if (full) {
            const float4* s0 = (const float4*)sm.stage[0];
            const float4* s1 = (const float4*)sm.stage[1];
            float4* o0 = (float4*)(out + 3 * Ns + blk0);
            float4* o1 = (float4*)(out + 5 * Ns + blk0);
            for (int j = tid; j < TILE / 4; j += TPB) { o0[j] = s0[j]; o1[j] = s1[j]; }
        } else {
            for (int j = tid; j < TILE; j += TPB)
                if (j < nrem) { out[3 * Ns + blk0 + j] = sm.stage[0][j]; out[5 * Ns + blk0 + j] = sm.stage[1][j]; }
        }
    }
}

// ---------------- serial fallback (N exceeds capacity) ---------------------
__global__ void __launch_bounds__(32, 1) track_seq_kernel(
    const float* __restrict__ time, const float* __restrict__ r0v,
    const float* __restrict__ d0v, const float* __restrict__ gptr,
    const float* __restrict__ b0ptr, const float* __restrict__ kuptr,
    float* __restrict__ out, int N)
{
    if (threadIdx.x != 0 || blockIdx.x != 0) return;
    const float C = 0.29979245f;
    const float dt = time[1] - time[0];
    const float dt2 = 0.5f * dt, h6 = dt * (1.0f / 6.0f);
    const float gamma = gptr[0], B0 = b0ptr[0], ku = kuptr[0];
    const float A = 1.0f / gamma;
    const float KdtA2 = ku * dt2 * A, KdtA = ku * dt * A;
    const float inv_cg = 1.0f / (C * gamma);
    float dx0 = d0v[0], dy0 = d0v[1], dz0 = d0v[2];
    float dn = sqrtf(dx0 * dx0 + dy0 * dy0 + dz0 * dz0);
    float pscale = C * sqrtf(gamma * gamma - 1.0f) / dn;
    float px = pscale * dx0, py = pscale * dy0, pz = pscale * dz0;
    float x = r0v[0], y = r0v[1], z = r0v[2];
    const float vy = py * A;
    float cps = cosf(ku * z), sps = sinf(ku * z);
    float Bc = B0 * cps, Bs = B0 * sps;
    const size_t Ns = (size_t)N;
    out[0] = x; out[Ns] = y; out[2 * Ns] = z;
    out[3 * Ns] = px * inv_cg; out[4 * Ns] = py * inv_cg; out[5 * Ns] = pz * inv_cg;
#pragma unroll 1
    for (int i = 1; i < N; ++i) {
        float vx1 = px * A, vz1 = pz * A;
        float apx1 = pz * Bc * A, apz1 = -px * Bc * A;
        float px2 = fmaf(apx1, dt2, px), pz2 = fmaf(apz1, dt2, pz);
        float d2 = KdtA2 * pz, q2 = d2 * d2;
        float sd2 = d2 * fmaf(-0.16666667f, q2, 1.0f), cd2 = fmaf(-0.5f, q2, 1.0f);
        float By2 = fmaf(Bc, cd2, -Bs * sd2);
        float vx2 = px2 * A, vz2 = pz2 * A;
        float apx2 = pz2 * By2 * A, apz2 = -px2 * By2 * A;
        float px3 = fmaf(apx2, dt2, px), pz3 = fmaf(apz2, dt2, pz);
        float d3 = KdtA2 * pz2, q3 = d3 * d3;
        float sd3 = d3 * fmaf(-0.16666667f, q3, 1.0f), cd3 = fmaf(-0.5f, q3, 1.0f);
        float By3 = fmaf(Bc, cd3, -Bs * sd3);
        float vx3 = px3 * A, vz3 = pz3 * A;
        float apx3 = pz3 * By3 * A, apz3 = -px3 * By3 * A;
        float px4 = fmaf(apx3, dt, px), pz4 = fmaf(apz3, dt, pz);
        float d4 = KdtA * pz3, q4 = d4 * d4;
        float sd4 = d4 * fmaf(-0.16666667f, q4, 1.0f), cd4 = fmaf(-0.5f, q4, 1.0f);
        float By4 = fmaf(Bc, cd4, -Bs * sd4);
        float vx4 = px4 * A, vz4 = pz4 * A;
        float apx4 = pz4 * By4 * A, apz4 = -px4 * By4 * A;
        float dxs = h6 * (vx1 + 2.0f * (vx2 + vx3) + vx4);
        float dzs = h6 * (vz1 + 2.0f * (vz2 + vz3) + vz4);
        px = px + h6 * (apx1 + 2.0f * (apx2 + apx3) + apx4);
        pz = pz + h6 * (apz1 + 2.0f * (apz2 + apz3) + apz4);
        x += dxs; y += dt * vy; z += dzs;
        float dp = ku * dzs, qp = dp * dp;
        float sdp = dp * fmaf(-0.16666667f, qp, 1.0f), cdp = fmaf(-0.5f, qp, 1.0f);
        float cn = fmaf(cps, cdp, -sps * sdp);
        float sn = fmaf(sps, cdp, cps * sdp);
        float nr = fmaf(cn, cn, sn * sn);
        float corr = fmaf(-0.5f, nr, 1.5f);
        cps = cn * corr; sps = sn * corr;
        Bc = B0 * cps; Bs = B0 * sps;
        out[i] = x; out[Ns + i] = y; out[2 * Ns + i] = z;
        out[3 * Ns + i] = px * inv_cg; out[4 * Ns + i] = py * inv_cg; out[5 * Ns + i] = pz * inv_cg;
    }
}

extern "C" void kernel_launch(void* const* d_in, const int* in_sizes, int n_in,
                              void* d_out, int out_size) {
    const float* time = (const float*)d_in[0];
    const float* r0   = (const float*)d_in[1];
    const float* d0   = (const float*)d_in[2];
    const float* gam  = (const float*)d_in[3];
    const float* B0   = (const float*)d_in[4];
    const float* ku   = (const float*)d_in[5];
    float* out = (float*)d_out;
    int N = in_sizes[0];

    if (N > CAP) {
        track_seq_kernel<<<1, 32>>>(time, r0, d0, gam, B0, ku, out, N);
        return;
    }
    picard_all<<<GRD, TPB>>>(time, r0, d0, gam, B0, ku, out, N);
}

// round 16
// speedup vs baseline: 1.4706x; 1.2699x over previous
#include <cuda_runtime.h>
#include <cuda_bf16.h>

// Persistent single-launch parallel-in-time undulator tracker.
// Numerics and loop structure IDENTICAL to the 43.7us R12 kernel (analytic
// Picard-1 init + final quantized-replication sweep, 4 centralized-barrier
// scans). R15 change: 2 co-resident CTAs per SM (TPB 512, GRD 296) so each
// CTA's serial scan sections / barrier spins are hidden by the sibling CTA.

#define TPB 512
#define NW  (TPB / 32)            // 16 warps
#define GRD 296
#define EPT 7
#define TILE (TPB * EPT)          // 3584
#define CAP (TILE * GRD)          // 1,060,864

__device__ volatile unsigned g_gen;   // monotonic across graph replays
__device__ unsigned g_cnt;
__device__ volatile float  g_totf[2][GRD];
__device__ volatile float  g_totf2[2][GRD];
__device__ volatile double g_totd[2][GRD];

struct SCon {
    float kuf, Kthf, Kzf, phi0f, f0f, cyf, y0f, x0f, scalef, byc, vzmdtf;
    float aampf, spsi0f;
    double z0, vzmdt, x0, y0;
};

struct SMem {
    __align__(16) float stage[2][TILE];   // 28 KB output transpose buffers
    SCon c;
    float  wf[NW], wf2[NW];
    double wd[NW];
    float  bf, bf2;
    double bd;
    unsigned base;
};

static __device__ __forceinline__ float warp_iscan_f(float v, int lane) {
#pragma unroll
    for (int d = 1; d < 32; d <<= 1) {
        float n = __shfl_up_sync(0xffffffffu, v, d);
        if (lane >= d) v += n;
    }
    return v;
}
static __device__ __forceinline__ double warp_iscan_d(double v, int lane) {
#pragma unroll
    for (int d = 1; d < 32; d <<= 1) {
        double n = __shfl_up_sync(0xffffffffu, v, d);
        if (lane >= d) v += n;
    }
    return v;
}
static __device__ __forceinline__ float warp_sum_f(float v) {
#pragma unroll
    for (int d = 16; d; d >>= 1) v += __shfl_down_sync(0xffffffffu, v, d);
    return v;
}
static __device__ __forceinline__ double warp_sum_d(double v) {
#pragma unroll
    for (int d = 16; d; d >>= 1) v += __shfl_down_sync(0xffffffffu, v, d);
    return v;
}

static __device__ __forceinline__ void grid_barrier(unsigned target) {
    __syncthreads();
    if (threadIdx.x == 0) {
        __threadfence();
        unsigned prev = atomicAdd(&g_cnt, 1u);
        if (prev == GRD - 1) {
            g_cnt = 0;
            __threadfence();
            g_gen = target;
        } else {
            while (g_gen != target) { }
            __threadfence();
        }
    }
    __syncthreads();
}

static __device__ float scan_f(SMem* sm, float tf, int sid, unsigned bg) {
    const int lane = threadIdx.x & 31, wid = threadIdx.x >> 5;
    const int buf = sid & 1;
    __syncthreads();
    float wf = warp_iscan_f(tf, lane);
    if (lane == 31) sm->wf[wid] = wf;
    __syncthreads();
    if (wid == 0) {
        float vf = (lane < NW) ? sm->wf[lane] : 0.f;
        float sf = warp_iscan_f(vf, lane);
        if (lane < NW) sm->wf[lane] = sf - vf;
        if (lane == 31) g_totf[buf][blockIdx.x] = sf;   // total (zeros padded)
    }
    grid_barrier(bg + (unsigned)sid + 1u);
    if (wid == 0) {
        float af = 0.f;
#pragma unroll
        for (int j = lane; j < GRD; j += 32)
            if (j < (int)blockIdx.x) af += g_totf[buf][j];
        af = warp_sum_f(af);
        if (lane == 0) sm->bf = af;
    }
    __syncthreads();
    return sm->bf + sm->wf[wid] + (wf - tf);
}

static __device__ double scan_d(SMem* sm, double td, int sid, unsigned bg) {
    const int lane = threadIdx.x & 31, wid = threadIdx.x >> 5;
    const int buf = sid & 1;
    __syncthreads();
    double wd = warp_iscan_d(td, lane);
    if (lane == 31) sm->wd[wid] = wd;
    __syncthreads();
    if (wid == 0) {
        double vd = (lane < NW) ? sm->wd[lane] : 0.0;
        double sd = warp_iscan_d(vd, lane);
        if (lane < NW) sm->wd[lane] = sd - vd;
        if (lane == 31) g_totd[buf][blockIdx.x] = sd;
    }
    grid_barrier(bg + (unsigned)sid + 1u);
    if (wid == 0) {
        double ad = 0.0;
#pragma unroll
        for (int j = lane; j < GRD; j += 32)
            if (j < (int)blockIdx.x) ad += g_totd[buf][j];
        ad = warp_sum_d(ad);
        if (lane == 0) sm->bd = ad;
    }
    __syncthreads();
    return sm->bd + sm->wd[wid] + (wd - td);
}

static __device__ void scan_fd(SMem* sm, float tf, double td, int sid,
                               unsigned bg, float& exf, double& exd) {
    const int lane = threadIdx.x & 31, wid = threadIdx.x >> 5;
    const int buf = sid & 1;
    __syncthreads();
    float wf = warp_iscan_f(tf, lane);
    double wd = warp_iscan_d(td, lane);
    if (lane == 31) { sm->wf[wid] = wf; sm->wd[wid] = wd; }
    __syncthreads();
    if (wid == 0) {
        float vf = (lane < NW) ? sm->wf[lane] : 0.f;
        double vd = (lane < NW) ? sm->wd[lane] : 0.0;
        float sf = warp_iscan_f(vf, lane);
        double sd = warp_iscan_d(vd, lane);
        if (lane < NW) { sm->wf[lane] = sf - vf; sm->wd[lane] = sd - vd; }
        if (lane == 31) { g_totf[buf][blockIdx.x] = sf; g_totd[buf][blockIdx.x] = sd; }
    }
    grid_barrier(bg + (unsigned)sid + 1u);
    if (wid == 0) {
        float af = 0.f; double ad = 0.0;
#pragma unroll
        for (int j = lane; j < GRD; j += 32)
            if (j < (int)blockIdx.x) { af += g_totf[buf][j]; ad += g_totd[buf][j]; }
        af = warp_sum_f(af); ad = warp_sum_d(ad);
        if (lane == 0) { sm->bf = af; sm->bd = ad; }
    }
    __syncthreads();
    exf = sm->bf + sm->wf[wid] + (wf - tf);
    exd = sm->bd + sm->wd[wid] + (wd - td);
}

static __device__ void scan_ff(SMem* sm, float ta, float tb, int sid,
                               unsigned bg, float& exa, float& exb) {
    const int lane = threadIdx.x & 31, wid = threadIdx.x >> 5;
    const int buf = sid & 1;
    __syncthreads();
    float wa = warp_iscan_f(ta, lane);
    float wb = warp_iscan_f(tb, lane);
    if (lane == 31) { sm->wf[wid] = wa; sm->wf2[wid] = wb; }
    __syncthreads();
    if (wid == 0) {
        float va = (lane < NW) ? sm->wf[lane] : 0.f;
        float vb = (lane < NW) ? sm->wf2[lane] : 0.f;
        float sa = warp_iscan_f(va, lane);
        float sb = warp_iscan_f(vb, lane);
        if (lane < NW) { sm->wf[lane] = sa - va; sm->wf2[lane] = sb - vb; }
        if (lane == 31) { g_totf[buf][blockIdx.x] = sa; g_totf2[buf][blockIdx.x] = sb; }
    }
    grid_barrier(bg + (unsigned)sid + 1u);
    if (wid == 0) {
        float aa = 0.f, ab = 0.f;
#pragma unroll
        for (int j = lane; j < GRD; j += 32)
            if (j < (int)blockIdx.x) { aa += g_totf[buf][j]; ab += g_totf2[buf][j]; }
        aa = warp_sum_f(aa); ab = warp_sum_f(ab);
        if (lane == 0) { sm->bf = aa; sm->bf2 = ab; }
    }
    __syncthreads();
    exa = sm->bf + sm->wf[wid] + (wa - ta);
    exb = sm->bf2 + sm->wf2[wid] + (wb - tb);
}

// f32-replicated field: psi = fl32(ku*z); 2-term Cody-Waite; fast cos.
static __device__ __forceinline__ float fval32(float kuf, float zf) {
    float psi = __fmul_rn(kuf, zf);
    float n = rintf(psi * 0.15915494309189535f);
    float r = fmaf(-n, 6.28125f, psi);
    r = fmaf(-n, 1.9353071795864769e-3f, r);
    return __cosf(r);
}
// sin(ku*z) for the analytic init (accuracy, not replication).
static __device__ __forceinline__ float sval32(float kuf, float zf) {
    float psi = __fmul_rn(kuf, zf);
    float n = rintf(psi * 0.15915494309189535f);
    float r = fmaf(-n, 6.28125f, psi);
    r = fmaf(-n, 1.9353071795864769e-3f, r);
    return __sinf(r);
}

// fl32(ref + c) - ref modeled as ulp(ref)-grid rounding of c (all f32).
static __device__ __forceinline__ float qstepf(float c, float ref) {
    int e = (int)((__float_as_uint(fabsf(ref)) >> 23) & 0xffu);
    if (e < 24) return c;
    float u  = __uint_as_float((unsigned)(e - 23) << 23);   // 2^(e-150)
    float iu = __uint_as_float((unsigned)(277 - e) << 23);  // 2^(150-e)
    return u * rintf(c * iu);
}

__global__ void __launch_bounds__(TPB, 2) picard_all(
    const float* __restrict__ time, const float* __restrict__ r0v,
    const float* __restrict__ d0v, const float* __restrict__ gptr,
    const float* __restrict__ b0ptr, const float* __restrict__ kuptr,
    float* __restrict__ out, int N)
{
    __shared__ SMem sm;
    const int tid = threadIdx.x;

    // ---- preamble: once per CTA (f64 transcendentals) ----
    if (tid == 0) {
        sm.base = g_gen;
        const double dt = (double)(time[1] - time[0]);
        const double gamma = (double)gptr[0];
        const double B0 = (double)b0ptr[0];
        const float kuf = kuptr[0];
        float dxf = d0v[0], dyf = d0v[1], dzf = d0v[2];
        float gf = gptr[0];
        float dnf = sqrtf(dxf * dxf + dyf * dyf + dzf * dzf);
        float csf = 0.29979245f * sqrtf(gf * gf - 1.0f);
        const double px0 = (double)(csf * dxf / dnf);
        const double py0 = (double)(csf * dyf / dnf);
        const double pz0 = (double)(csf * dzf / dnf);
        const double x0 = (double)r0v[0], y0 = (double)r0v[1], z0 = (double)r0v[2];
        const double invg = 1.0 / gamma;
        const double Pmag = sqrt(px0 * px0 + pz0 * pz0);
        const double phi0 = atan2(px0, pz0);
        const double cy = dt * py0 * invg;
        const double ku_d = (double)kuf;
        const double psi0 = ku_d * z0;
        // secular-corrected ballistic mean velocity
        const double vz0d = pz0 * invg;
        const double a0 = B0 * invg / (ku_d * vz0d);
        const double bph = phi0 - a0 * sin(psi0);
        const double a2 = a0 * a0;
        const double j0a = 1.0 - 0.25 * a2 + a2 * a2 / 64.0;
        const double vzm = Pmag * invg * cos(bph) * j0a;
        const double vzmdt = vzm * dt;
        const double aamp = B0 * invg / (ku_d * vzm);   // analytic theta amplitude

        sm.c.kuf = kuf;
        sm.c.Kthf = (float)(B0 * dt * invg);
        sm.c.Kzf  = (float)(dt * invg * Pmag);
        sm.c.phi0f = (float)phi0;
        sm.c.f0f = fval32(kuf, (float)z0);
        sm.c.cyf = (float)cy;
        sm.c.y0f = (float)y0;
        sm.c.x0f = (float)x0;
        sm.c.scalef = (float)(Pmag / (0.29979245 * gamma));
        sm.c.byc    = (float)(py0 / (0.29979245 * gamma));
        sm.c.vzmdtf = (float)vzmdt;
        sm.c.aampf  = (float)aamp;
        sm.c.spsi0f = (float)sin(psi0);
        sm.c.z0 = z0; sm.c.vzmdt = vzmdt; sm.c.x0 = x0; sm.c.y0 = y0;
    }
    __syncthreads();

    const unsigned bg = sm.base;
    const float kuf = sm.c.kuf, Kthf = sm.c.Kthf, Kzf = sm.c.Kzf;
    const float phi0f = sm.c.phi0f, f0f = sm.c.f0f, cyf = sm.c.cyf;
    const float y0f = sm.c.y0f, x0f = sm.c.x0f;
    const float scalef = sm.c.scalef, byc = sm.c.byc, vzmdtf = sm.c.vzmdtf;
    const float aampf = sm.c.aampf, spsi0f = sm.c.spsi0f;
    const double z0 = sm.c.z0;

    const int base = ((int)blockIdx.x * TPB + tid) * EPT;
    const int blk0 = (int)blockIdx.x * TILE;

    float zf[EPT], fs[EPT], qs[EPT], cxs[EPT];
    int sid = 0;

    // ---- init: analytic Picard-1 (no f-scan; 1 q-scan) ----
    {
        double zb = z0 + sm.c.vzmdt * (double)base;
        float zbhi = (float)zb;
        float zblo = (float)(zb - (double)zbhi);
        float Tq = 0.f;
#pragma unroll
        for (int k = 0; k < EPT; ++k) {
            int i = base + k;
            float zball = zbhi + (zblo + (float)k * vzmdtf);
            float zmid  = zbhi + (zblo + ((float)k + 0.5f) * vzmdtf);
            float th = aampf * (sval32(kuf, zmid) - spsi0f);
            float u = phi0f + th;
            float u2 = u * u;
            float cu = fmaf(u2, fmaf(u2, 1.f / 24.f, -0.5f), 1.f);
            float qf = (i < N) ? qstepf(Kzf * cu, zball) : 0.f;
            qs[k] = qf;
            Tq += qf;                          // exact (grid multiples)
        }
        double exq = scan_d(&sm, (double)Tq, sid, bg); sid++;

        double basez = z0 + exq;
        float bzhi = (float)basez;
        float bzlo = (float)(basez - (double)bzhi);
        float runq = 0.f;
#pragma unroll
        for (int k = 0; k < EPT; ++k) {
            zf[k] = bzhi + (bzlo + runq);
            runq += qs[k];                     // exact f32 chain
        }
    }

    // ---- final sweep: field scan ----
    float Tf = 0.f;
#pragma unroll
    for (int k = 0; k < EPT; ++k) {
        int i = base + k;
        float f = (i < N) ? fval32(kuf, zf[k]) : 0.f;
        fs[k] = f; Tf += f;
    }
    float exf = scan_f(&sm, Tf, sid, bg); sid++;

    float Tq = 0.f, Tcx = 0.f; float run = exf;
#pragma unroll
    for (int k = 0; k < EPT; ++k) {
        int i = base + k;
        float f = fs[k];
        run += f;
        float th  = Kthf * (run - 0.5f * (f0f + f));
        float thm = fmaf(0.5f * Kthf, f, th);
        float u = phi0f + thm;
        float u2 = u * u;
        float cu = fmaf(u2, fmaf(u2, 1.f / 24.f, -0.5f), 1.f);
        float su = u * fmaf(u2, fmaf(u2, 1.f / 120.f, -1.f / 6.f), 1.f);
        float qf = (i < N) ? qstepf(Kzf * cu, zf[k]) : 0.f;
        float cx = (i < N) ? Kzf * su : 0.f;
        qs[k] = qf;   Tq += qf;
        cxs[k] = cx;  Tcx += cx;
        fs[k] = th;                            // keep node theta
    }
    float excx; double exq;
    scan_fd(&sm, Tcx, (double)Tq, sid, bg, excx, exq); sid++;

    float Tqx = 0.f, Tqy = 0.f;
    {
        double basez = z0 + exq;
        float bzhi = (float)basez;
        float bzlo = (float)(basez - (double)bzhi);
        float runq = 0.f, runcx = excx;
#pragma unroll
        for (int k = 0; k < EPT; ++k) {
            int i = base + k;
            zf[k] = bzhi + (bzlo + runq);
            runq += qs[k];
            float xpl = x0f + runcx;                 // plain x (binade ref)
            runcx += cxs[k];
            float qx = (i < N) ? qstepf(cxs[k], xpl) : 0.f;
            cxs[k] = qx;  Tqx += qx;
            float ypl = fmaf(cyf, (float)i, y0f);    // plain y (binade ref)
            float qy = (i < N) ? qstepf(cyf, ypl) : 0.f;
            qs[k] = qy;   Tqy += qy;
        }
    }
    float exqx, exqy;
    scan_ff(&sm, Tqx, Tqy, sid, bg, exqx, exqy); sid++;

    // ---- outputs (smem transpose, coalesced float4) ----
    const size_t Ns = (size_t)N;
    const int nrem = N - blk0;
    const bool full = (nrem >= TILE) && ((Ns & 3u) == 0) && ((blk0 & 3) == 0);

    // pass 1: x (stage 0), y (stage 1)
    {
        double basex = sm.c.x0 + (double)exqx;
        float bxhi = (float)basex;
        float bxlo = (float)(basex - (double)bxhi);
        double basey = sm.c.y0 + (double)exqy;
        float byhi = (float)basey;
        float bylo = (float)(basey - (double)byhi);
        float runqx = 0.f, runqy = 0.f;
        __syncthreads();
#pragma unroll
        for (int k = 0; k < EPT; ++k) {
            sm.stage[0][tid * EPT + k] = bxhi + (bxlo + runqx);
            sm.stage[1][tid * EPT + k] = byhi + (bylo + runqy);
            runqx += cxs[k];
            runqy += qs[k];
        }
        __syncthreads();
        if (full) {
            const float4* s0 = (const float4*)sm.stage[0];
            const float4* s1 = (const float4*)sm.stage[1];
            float4* o0 = (float4*)(out + blk0);
            float4* o1 = (float4*)(out + Ns + blk0);
            for (int j = tid; j < TILE / 4; j += TPB) { o0[j] = s0[j]; o1[j] = s1[j]; }
        } else {
            for (int j = tid; j < TILE; j += TPB)
                if (j < nrem) { out[blk0 + j] = sm.stage[0][j]; out[Ns + blk0 + j] = sm.stage[1][j]; }
        }
    }
    // pass 2: z (stage 0), beta_y constant direct
    {
        __syncthreads();
#pragma unroll
        for (int k = 0; k < EPT; ++k)
            sm.stage[0][tid * EPT + k] = zf[k];
        __syncthreads();
        if (full) {
            const float4* s0 = (const float4*)sm.stage[0];
            float4* o0 = (float4*)(out + 2 * Ns + blk0);
            float4* o1 = (float4*)(out + 4 * Ns + blk0);
            float4 cv = make_float4(byc, byc, byc, byc);
            for (int j = tid; j < TILE / 4; j += TPB) { o0[j] = s0[j]; o1[j] = cv; }
        } else {
            for (int j = tid; j < TILE; j += TPB)
                if (j < nrem) { out[2 * Ns + blk0 + j] = sm.stage[0][j]; out[4 * Ns + blk0 + j] = byc; }
        }
    }
    // pass 3: beta_x (stage 0), beta_z (stage 1) — share u-poly
    {
        __syncthreads();
#pragma unroll
        for (int k = 0; k < EPT; ++k) {
            float u = phi0f + fs[k];
            float u2 = u * u;
            float su = u * fmaf(u2, fmaf(u2, 1.f / 120.f, -1.f / 6.f), 1.f);
            float cu = fmaf(u2, fmaf(u2, 1.f / 24.f, -0.5f), 1.f);
            sm.stage[0][tid * EPT + k] = scalef * su;
            sm.stage[1][tid * EPT + k] = scalef * cu;
        }
        __syncthreads();
        if (full) {
            const float4* s0 = (const float4*)sm.stage[0];
            const float4* s1 = (const float4*)sm.stage[1];
            float4* o0 = (float4*)(out + 3 * Ns + blk0);
            float4* o1 = (float4*)(out + 5 * Ns + blk0);
            for (int j = tid; j < TILE / 4; j += TPB) { o0[j] = s0[j]; o1[j] = s1[j]; }
        } else {
            for (int j = tid; j < TILE; j += TPB)
                if (j < nrem) { out[3 * Ns + blk0 + j] = sm.stage[0][j]; out[5 * Ns + blk0 + j] = sm.stage[1][j]; }
        }
    }
}

// ---------------- serial fallback (N exceeds capacity) ---------------------
__global__ void __launch_bounds__(32, 1) track_seq_kernel(
    const float* __restrict__ time, const float* __restrict__ r0v,
    const float* __restrict__ d0v, const float* __restrict__ gptr,
    const float* __restrict__ b0ptr, const float* __restrict__ kuptr,
    float* __restrict__ out, int N)
{
    if (threadIdx.x != 0 || blockIdx.x != 0) return;
    const float C = 0.29979245f;
    const float dt = time[1] - time[0];
    const float dt2 = 0.5f * dt, h6 = dt * (1.0f / 6.0f);
    const float gamma = gptr[0], B0 = b0ptr[0], ku = kuptr[0];
    const float A = 1.0f / gamma;
    const float KdtA2 = ku * dt2 * A, KdtA = ku * dt * A;
    const float inv_cg = 1.0f / (C * gamma);
    float dx0 = d0v[0], dy0 = d0v[1], dz0 = d0v[2];
    float dn = sqrtf(dx0 * dx0 + dy0 * dy0 + dz0 * dz0);
    float pscale = C * sqrtf(gamma * gamma - 1.0f) / dn;
    float px = pscale * dx0, py = pscale * dy0, pz = pscale * dz0;
    float x = r0v[0], y = r0v[1], z = r0v[2];
    const float vy = py * A;
    float cps = cosf(ku * z), sps = sinf(ku * z);
    float Bc = B0 * cps, Bs = B0 * sps;
    const size_t Ns = (size_t)N;
    out[0] = x; out[Ns] = y; out[2 * Ns] = z;
    out[3 * Ns] = px * inv_cg; out[4 * Ns] = py * inv_cg; out[5 * Ns] = pz * inv_cg;
#pragma unroll 1
    for (int i = 1; i < N; ++i) {
        float vx1 = px * A, vz1 = pz * A;
        float apx1 = pz * Bc * A, apz1 = -px * Bc * A;
        float px2 = fmaf(apx1, dt2, px), pz2 = fmaf(apz1, dt2, pz);
        float d2 = KdtA2 * pz, q2 = d2 * d2;
        float sd2 = d2 * fmaf(-0.16666667f, q2, 1.0f), cd2 = fmaf(-0.5f, q2, 1.0f);
        float By2 = fmaf(Bc, cd2, -Bs * sd2);
        float vx2 = px2 * A, vz2 = pz2 * A;
        float apx2 = pz2 * By2 * A, apz2 = -px2 * By2 * A;
        float px3 = fmaf(apx2, dt2, px), pz3 = fmaf(apz2, dt2, pz);
        float d3 = KdtA2 * pz2, q3 = d3 * d3;
        float sd3 = d3 * fmaf(-0.16666667f, q3, 1.0f), cd3 = fmaf(-0.5f, q3, 1.0f);
        float By3 = fmaf(Bc, cd3, -Bs * sd3);
        float vx3 = px3 * A, vz3 = pz3 * A;
        float apx3 = pz3 * By3 * A, apz3 = -px3 * By3 * A;
        float px4 = fmaf(apx3, dt, px), pz4 = fmaf(apz3, dt, pz);
        float d4 = KdtA * pz3, q4 = d4 * d4;
        float sd4 = d4 * fmaf(-0.16666667f, q4, 1.0f), cd4 = fmaf(-0.5f, q4, 1.0f);
        float By4 = fmaf(Bc, cd4, -Bs * sd4);
        float vx4 = px4 * A, vz4 = pz4 * A;
        float apx4 = pz4 * By4 * A, apz4 = -px4 * By4 * A;
        float dxs = h6 * (vx1 + 2.0f * (vx2 + vx3) + vx4);
        float dzs = h6 * (vz1 + 2.0f * (vz2 + vz3) + vz4);
        px = px + h6 * (apx1 + 2.0f * (apx2 + apx3) + apx4);
        pz = pz + h6 * (apz1 + 2.0f * (apz2 + apz3) + apz4);
        x += dxs; y += dt * vy; z += dzs;
        float dp = ku * dzs, qp = dp * dp;
        float sdp = dp * fmaf(-0.16666667f, qp, 1.0f), cdp = fmaf(-0.5f, qp, 1.0f);
        float cn = fmaf(cps, cdp, -sps * sdp);
        float sn = fmaf(sps, cdp, cps * sdp);
        float nr = fmaf(cn, cn, sn * sn);
        float corr = fmaf(-0.5f, nr, 1.5f);
        cps = cn * corr; sps = sn * corr;
        Bc = B0 * cps; Bs = B0 * sps;
        out[i] = x; out[Ns + i] = y; out[2 * Ns + i] = z;
        out[3 * Ns + i] = px * inv_cg; out[4 * Ns + i] = py * inv_cg; out[5 * Ns + i] = pz * inv_cg;
    }
}

extern "C" void kernel_launch(void* const* d_in, const int* in_sizes, int n_in,
                              void* d_out, int out_size) {
    const float* time = (const float*)d_in[0];
    const float* r0   = (const float*)d_in[1];
    const float* d0   = (const float*)d_in[2];
    const float* gam  = (const float*)d_in[3];
    const float* B0   = (const float*)d_in[4];
    const float* ku   = (const float*)d_in[5];
    float* out = (float*)d_out;
    int N = in_sizes[0];

    if (N > CAP) {
        track_seq_kernel<<<1, 32>>>(time, r0, d0, gam, B0, ku, out, N);
        return;
    }
    picard_all<<<GRD, TPB>>>(time, r0, d0, gam, B0, ku, out, N);
}

// round 17
// speedup vs baseline: 1.5444x; 1.0502x over previous
#include <cuda_runtime.h>
#include <cuda_bf16.h>

// Persistent single-launch parallel-in-time undulator tracker.
// Numerics IDENTICAL to the 43.5us R16 kernel (analytic Picard-1 init +
// final quantized-replication sweep, 4 scans, 296x512, 2 CTAs/SM).
// R17: scans split into publish/finish; independent work runs in each
// barrier's shadow (Tqy total; beta_y writes; z + beta_x/beta_z passes).

#define TPB 512
#define NW  (TPB / 32)            // 16 warps
#define GRD 296
#define EPT 7
#define TILE (TPB * EPT)          // 3584
#define CAP (TILE * GRD)          // 1,060,864

__device__ volatile unsigned g_gen;   // monotonic across graph replays
__device__ unsigned g_cnt;
__device__ volatile float  g_totf[2][GRD];
__device__ volatile float  g_totf2[2][GRD];
__device__ volatile double g_totd[2][GRD];

struct SCon {
    float kuf, Kthf, Kzf, phi0f, f0f, cyf, y0f, x0f, scalef, byc, vzmdtf;
    float aampf, spsi0f;
    double z0, vzmdt, x0, y0;
};

struct SMem {
    __align__(16) float stage[2][TILE];   // 28 KB output transpose buffers
    SCon c;
    float  wf[NW], wf2[NW];
    double wd[NW];
    float  bf, bf2;
    double bd;
    unsigned base;
};

static __device__ __forceinline__ float warp_iscan_f(float v, int lane) {
#pragma unroll
    for (int d = 1; d < 32; d <<= 1) {
        float n = __shfl_up_sync(0xffffffffu, v, d);
        if (lane >= d) v += n;
    }
    return v;
}
static __device__ __forceinline__ double warp_iscan_d(double v, int lane) {
#pragma unroll
    for (int d = 1; d < 32; d <<= 1) {
        double n = __shfl_up_sync(0xffffffffu, v, d);
        if (lane >= d) v += n;
    }
    return v;
}
static __device__ __forceinline__ float warp_sum_f(float v) {
#pragma unroll
    for (int d = 16; d; d >>= 1) v += __shfl_down_sync(0xffffffffu, v, d);
    return v;
}
static __device__ __forceinline__ double warp_sum_d(double v) {
#pragma unroll
    for (int d = 16; d; d >>= 1) v += __shfl_down_sync(0xffffffffu, v, d);
    return v;
}

// Arrival half of the barrier (non-blocking). Totals must be in gmem first.
static __device__ __forceinline__ void arrive(unsigned tgt) {
    __syncthreads();
    if (threadIdx.x == 0) {
        __threadfence();
        unsigned prev = atomicAdd(&g_cnt, 1u);
        if (prev == GRD - 1) {
            g_cnt = 0;
            __threadfence();
            g_gen = tgt;
        }
    }
}
// Blocking half.
static __device__ __forceinline__ void waitgen(unsigned tgt) {
    if (threadIdx.x == 0) {
        while (g_gen != tgt) { }
        __threadfence();
    }
    __syncthreads();
}

// ---- split scans: publish (block scan + totals + arrive) / finish ----
static __device__ double scand_pub(SMem* sm, double td, int buf, unsigned tgt) {
    const int lane = threadIdx.x & 31, wid = threadIdx.x >> 5;
    __syncthreads();
    double wd = warp_iscan_d(td, lane);
    if (lane == 31) sm->wd[wid] = wd;
    __syncthreads();
    if (wid == 0) {
        double vd = (lane < NW) ? sm->wd[lane] : 0.0;
        double sd = warp_iscan_d(vd, lane);
        if (lane < NW) sm->wd[lane] = sd - vd;
        if (lane == 31) g_totd[buf][blockIdx.x] = sd;
    }
    arrive(tgt);
    return wd - td;
}
static __device__ double scand_fin(SMem* sm, double res, int buf, unsigned tgt) {
    const int lane = threadIdx.x & 31, wid = threadIdx.x >> 5;
    waitgen(tgt);
    if (wid == 0) {
        double ad = 0.0;
#pragma unroll
        for (int j = lane; j < GRD; j += 32)
            if (j < (int)blockIdx.x) ad += g_totd[buf][j];
        ad = warp_sum_d(ad);
        if (lane == 0) sm->bd = ad;
    }
    __syncthreads();
    return sm->bd + sm->wd[wid] + res;
}

static __device__ float scanf_pub(SMem* sm, float tf, int buf, unsigned tgt) {
    const int lane = threadIdx.x & 31, wid = threadIdx.x >> 5;
    __syncthreads();
    float wf = warp_iscan_f(tf, lane);
    if (lane == 31) sm->wf[wid] = wf;
    __syncthreads();
    if (wid == 0) {
        float vf = (lane < NW) ? sm->wf[lane] : 0.f;
        float sf = warp_iscan_f(vf, lane);
        if (lane < NW) sm->wf[lane] = sf - vf;
        if (lane == 31) g_totf[buf][blockIdx.x] = sf;
    }
    arrive(tgt);
    return wf - tf;
}
static __device__ float scanf_fin(SMem* sm, float res, int buf, unsigned tgt) {
    const int lane = threadIdx.x & 31, wid = threadIdx.x >> 5;
    waitgen(tgt);
    if (wid == 0) {
        float af = 0.f;
#pragma unroll
        for (int j = lane; j < GRD; j += 32)
            if (j < (int)blockIdx.x) af += g_totf[buf][j];
        af = warp_sum_f(af);
        if (lane == 0) sm->bf = af;
    }
    __syncthreads();
    return sm->bf + sm->wf[wid] + res;
}

static __device__ void scanfd_pub(SMem* sm, float tf, double td, int buf,
                                  unsigned tgt, float& rf, double& rd) {
    const int lane = threadIdx.x & 31, wid = threadIdx.x >> 5;
    __syncthreads();
    float wf = warp_iscan_f(tf, lane);
    double wd = warp_iscan_d(td, lane);
    if (lane == 31) { sm->wf[wid] = wf; sm->wd[wid] = wd; }
    __syncthreads();
    if (wid == 0) {
        float vf = (lane < NW) ? sm->wf[lane] : 0.f;
        double vd = (lane < NW) ? sm->wd[lane] : 0.0;
        float sf = warp_iscan_f(vf, lane);
        double sd = warp_iscan_d(vd, lane);
        if (lane < NW) { sm->wf[lane] = sf - vf; sm->wd[lane] = sd - vd; }
        if (lane == 31) { g_totf[buf][blockIdx.x] = sf; g_totd[buf][blockIdx.x] = sd; }
    }
    arrive(tgt);
    rf = wf - tf; rd = wd - td;
}
static __device__ void scanfd_fin(SMem* sm, float rf, double rd, int buf,
                                  unsigned tgt, float& exf, double& exd) {
    const int lane = threadIdx.x & 31, wid = threadIdx.x >> 5;
    waitgen(tgt);
    if (wid == 0) {
        float af = 0.f; double ad = 0.0;
#pragma unroll
        for (int j = lane; j < GRD; j += 32)
            if (j < (int)blockIdx.x) { af += g_totf[buf][j]; ad += g_totd[buf][j]; }
        af = warp_sum_f(af); ad = warp_sum_d(ad);
        if (lane == 0) { sm->bf = af; sm->bd = ad; }
    }
    __syncthreads();
    exf = sm->bf + sm->wf[wid] + rf;
    exd = sm->bd + sm->wd[wid] + rd;
}

static __device__ void scanff_pub(SMem* sm, float ta, float tb, int buf,
                                  unsigned tgt, float& ra, float& rb) {
    const int lane = threadIdx.x & 31, wid = threadIdx.x >> 5;
    __syncthreads();
    float wa = warp_iscan_f(ta, lane);
    float wb = warp_iscan_f(tb, lane);
    if (lane == 31) { sm->wf[wid] = wa; sm->wf2[wid] = wb; }
    __syncthreads();
    if (wid == 0) {
        float va = (lane < NW) ? sm->wf[lane] : 0.f;
        float vb = (lane < NW) ? sm->wf2[lane] : 0.f;
        float sa = warp_iscan_f(va, lane);
        float sb = warp_iscan_f(vb, lane);
        if (lane < NW) { sm->wf[lane] = sa - va; sm->wf2[lane] = sb - vb; }
        if (lane == 31) { g_totf[buf][blockIdx.x] = sa; g_totf2[buf][blockIdx.x] = sb; }
    }
    arrive(tgt);
    ra = wa - ta; rb = wb - tb;
}
static __device__ void scanff_fin(SMem* sm, float ra, float rb, int buf,
                                  unsigned tgt, float& exa, float& exb) {
    const int lane = threadIdx.x & 31, wid = threadIdx.x >> 5;
    waitgen(tgt);
    if (wid == 0) {
        float aa = 0.f, ab = 0.f;
#pragma unroll
        for (int j = lane; j < GRD; j += 32)
            if (j < (int)blockIdx.x) { aa += g_totf[buf][j]; ab += g_totf2[buf][j]; }
        aa = warp_sum_f(aa); ab = warp_sum_f(ab);
        if (lane == 0) { sm->bf = aa; sm->bf2 = ab; }
    }
    __syncthreads();
    exa = sm->bf + sm->wf[wid] + ra;
    exb = sm->bf2 + sm->wf2[wid] + rb;
}

// f32-replicated field: psi = fl32(ku*z); 2-term Cody-Waite; fast cos.
static __device__ __forceinline__ float fval32(float kuf, float zf) {
    float psi = __fmul_rn(kuf, zf);
    float n = rintf(psi * 0.15915494309189535f);
    float r = fmaf(-n, 6.28125f, psi);
    r = fmaf(-n, 1.9353071795864769e-3f, r);
    return __cosf(r);
}
// sin(ku*z) for the analytic init (accuracy, not replication).
static __device__ __forceinline__ float sval32(float kuf, float zf) {
    float psi = __fmul_rn(kuf, zf);
    float n = rintf(psi * 0.15915494309189535f);
    float r = fmaf(-n, 6.28125f, psi);
    r = fmaf(-n, 1.9353071795864769e-3f, r);
    return __sinf(r);
}

// fl32(ref + c) - ref modeled as ulp(ref)-grid rounding of c (all f32).
static __device__ __forceinline__ float qstepf(float c, float ref) {
    int e = (int)((__float_as_uint(fabsf(ref)) >> 23) & 0xffu);
    if (e < 24) return c;
    float u  = __uint_as_float((unsigned)(e - 23) << 23);   // 2^(e-150)
    float iu = __uint_as_float((unsigned)(277 - e) << 23);  // 2^(150-e)
    return u * rintf(c * iu);
}

__global__ void __launch_bounds__(TPB, 2) picard_all(
    const float* __restrict__ time, const float* __restrict__ r0v,
    const float* __restrict__ d0v, const float* __restrict__ gptr,
    const float* __restrict__ b0ptr, const float* __restrict__ kuptr,
    float* __restrict__ out, int N)
{
    __shared__ SMem sm;
    const int tid = threadIdx.x;

    // ---- preamble: once per CTA (f64 transcendentals) ----
    if (tid == 0) {
        sm.base = g_gen;
        const double dt = (double)(time[1] - time[0]);
        const double gamma = (double)gptr[0];
        const double B0 = (double)b0ptr[0];
        const float kuf = kuptr[0];
        float dxf = d0v[0], dyf = d0v[1], dzf = d0v[2];
        float gf = gptr[0];
        float dnf = sqrtf(dxf * dxf + dyf * dyf + dzf * dzf);
        float csf = 0.29979245f * sqrtf(gf * gf - 1.0f);
        const double px0 = (double)(csf * dxf / dnf);
        const double py0 = (double)(csf * dyf / dnf);
        const double pz0 = (double)(csf * dzf / dnf);
        const double x0 = (double)r0v[0], y0 = (double)r0v[1], z0 = (double)r0v[2];
        const double invg = 1.0 / gamma;
        const double Pmag = sqrt(px0 * px0 + pz0 * pz0);
        const double phi0 = atan2(px0, pz0);
        const double cy = dt * py0 * invg;
        const double ku_d = (double)kuf;
        const double psi0 = ku_d * z0;
        const double vz0d = pz0 * invg;
        const double a0 = B0 * invg / (ku_d * vz0d);
        const double bph = phi0 - a0 * sin(psi0);
        const double a2 = a0 * a0;
        const double j0a = 1.0 - 0.25 * a2 + a2 * a2 / 64.0;
        const double vzm = Pmag * invg * cos(bph) * j0a;
        const double vzmdt = vzm * dt;
        const double aamp = B0 * invg / (ku_d * vzm);

        sm.c.kuf = kuf;
        sm.c.Kthf = (float)(B0 * dt * invg);
        sm.c.Kzf  = (float)(dt * invg * Pmag);
        sm.c.phi0f = (float)phi0;
        sm.c.f0f = fval32(kuf, (float)z0);
        sm.c.cyf = (float)cy;
        sm.c.y0f = (float)y0;
        sm.c.x0f = (float)x0;
        sm.c.scalef = (float)(Pmag / (0.29979245 * gamma));
        sm.c.byc    = (float)(py0 / (0.29979245 * gamma));
        sm.c.vzmdtf = (float)vzmdt;
        sm.c.aampf  = (float)aamp;
        sm.c.spsi0f = (float)sin(psi0);
        sm.c.z0 = z0; sm.c.vzmdt = vzmdt; sm.c.x0 = x0; sm.c.y0 = y0;
    }
    __syncthreads();

    const unsigned bg = sm.base;
    const float kuf = sm.c.kuf, Kthf = sm.c.Kthf, Kzf = sm.c.Kzf;
    const float phi0f = sm.c.phi0f, f0f = sm.c.f0f, cyf = sm.c.cyf;
    const float y0f = sm.c.y0f, x0f = sm.c.x0f;
    const float scalef = sm.c.scalef, byc = sm.c.byc, vzmdtf = sm.c.vzmdtf;
    const float aampf = sm.c.aampf, spsi0f = sm.c.spsi0f;
    const double z0 = sm.c.z0;

    const int base = ((int)blockIdx.x * TPB + tid) * EPT;
    const int blk0 = (int)blockIdx.x * TILE;
    const size_t Ns = (size_t)N;
    const int nrem = N - blk0;
    const bool full = (nrem >= TILE) && ((Ns & 3u) == 0) && ((blk0 & 3) == 0);

    float zf[EPT], fs[EPT], qs[EPT], cxs[EPT];

    // ---- init: analytic Picard-1 (1 q-scan) ----
    {
        double zb = z0 + sm.c.vzmdt * (double)base;
        float zbhi = (float)zb;
        float zblo = (float)(zb - (double)zbhi);
        float Tq = 0.f;
#pragma unroll
        for (int k = 0; k < EPT; ++k) {
            int i = base + k;
            float zball = zbhi + (zblo + (float)k * vzmdtf);
            float zmid  = zbhi + (zblo + ((float)k + 0.5f) * vzmdtf);
            float th = aampf * (sval32(kuf, zmid) - spsi0f);
            float u = phi0f + th;
            float u2 = u * u;
            float cu = fmaf(u2, fmaf(u2, 1.f / 24.f, -0.5f), 1.f);
            float qf = (i < N) ? qstepf(Kzf * cu, zball) : 0.f;
            qs[k] = qf;
            Tq += qf;
        }
        double rd = scand_pub(&sm, (double)Tq, 0, bg + 1u);
        double exq = scand_fin(&sm, rd, 0, bg + 1u);

        double basez = z0 + exq;
        float bzhi = (float)basez;
        float bzlo = (float)(basez - (double)bzhi);
        float runq = 0.f;
#pragma unroll
        for (int k = 0; k < EPT; ++k) {
            zf[k] = bzhi + (bzlo + runq);
            runq += qs[k];
        }
    }

    // ---- field scan (shadow: Tqy total) ----
    float Tf = 0.f;
#pragma unroll
    for (int k = 0; k < EPT; ++k) {
        int i = base + k;
        float f = (i < N) ? fval32(kuf, zf[k]) : 0.f;
        fs[k] = f; Tf += f;
    }
    float rf = scanf_pub(&sm, Tf, 1, bg + 2u);
    float Tqy = 0.f;
#pragma unroll
    for (int k = 0; k < EPT; ++k) {
        int i = base + k;
        float ypl = fmaf(cyf, (float)i, y0f);
        Tqy += (i < N) ? qstepf(cyf, ypl) : 0.f;
    }
    float exf = scanf_fin(&sm, rf, 1, bg + 2u);

    // ---- theta + qz + plain-x increments; fd scan (shadow: beta_y writes) ----
    float Tq = 0.f, Tcx = 0.f; float run = exf;
#pragma unroll
    for (int k = 0; k < EPT; ++k) {
        int i = base + k;
        float f = fs[k];
        run += f;
        float th  = Kthf * (run - 0.5f * (f0f + f));
        float thm = fmaf(0.5f * Kthf, f, th);
        float u = phi0f + thm;
        float u2 = u * u;
        float cu = fmaf(u2, fmaf(u2, 1.f / 24.f, -0.5f), 1.f);
        float su = u * fmaf(u2, fmaf(u2, 1.f / 120.f, -1.f / 6.f), 1.f);
        float qf = (i < N) ? qstepf(Kzf * cu, zf[k]) : 0.f;
        float cx = (i < N) ? Kzf * su : 0.f;
        qs[k] = qf;   Tq += qf;
        cxs[k] = cx;  Tcx += cx;
        fs[k] = th;
    }
    float rfc; double rdq;
    scanfd_pub(&sm, Tcx, (double)Tq, 0, bg + 3u, rfc, rdq);
    // shadow: beta_y constant output (fully independent)
    if (full) {
        float4 cv = make_float4(byc, byc, byc, byc);
        float4* o1 = (float4*)(out + 4 * Ns + blk0);
        for (int j = tid; j < TILE / 4; j += TPB) o1[j] = cv;
    } else {
        for (int j = tid; j < TILE; j += TPB)
            if (j < nrem) out[4 * Ns + blk0 + j] = byc;
    }
    float excx; double exq;
    scanfd_fin(&sm, rfc, rdq, 0, bg + 3u, excx, exq);

    // ---- z-ladder + quantized-x increments; ff scan (shadow: z + betas) ----
    float Tqx = 0.f;
    {
        double basez = z0 + exq;
        float bzhi = (float)basez;
        float bzlo = (float)(basez - (double)bzhi);
        float runq = 0.f, runcx = excx;
#pragma unroll
        for (int k = 0; k < EPT; ++k) {
            int i = base + k;
            zf[k] = bzhi + (bzlo + runq);
            runq += qs[k];
            float xpl = x0f + runcx;
            runcx += cxs[k];
            float qx = (i < N) ? qstepf(cxs[k], xpl) : 0.f;
            cxs[k] = qx;  Tqx += qx;
        }
    }
    float ra, rb;
    scanff_pub(&sm, Tqx, Tqy, 1, bg + 4u, ra, rb);

    // shadow pass A: z output
    __syncthreads();
#pragma unroll
    for (int k = 0; k < EPT; ++k)
        sm.stage[0][tid * EPT + k] = zf[k];
    __syncthreads();
    if (full) {
        const float4* s0 = (const float4*)sm.stage[0];
        float4* o0 = (float4*)(out + 2 * Ns + blk0);
        for (int j = tid; j < TILE / 4; j += TPB) o0[j] = s0[j];
    } else {
        for (int j = tid; j < TILE; j += TPB)
            if (j < nrem) out[2 * Ns + blk0 + j] = sm.stage[0][j];
    }
    // shadow pass B: beta_x, beta_z (share u-poly on node theta)
    __syncthreads();
#pragma unroll
    for (int k = 0; k < EPT; ++k) {
        float u = phi0f + fs[k];
        float u2 = u * u;
        float su = u * fmaf(u2, fmaf(u2, 1.f / 120.f, -1.f / 6.f), 1.f);
        float cu = fmaf(u2, fmaf(u2, 1.f / 24.f, -0.5f), 1.f);
        sm.stage[0][tid * EPT + k] = scalef * su;
        sm.stage[1][tid * EPT + k] = scalef * cu;
    }
    __syncthreads();
    if (full) {
        const float4* s0 = (const float4*)sm.stage[0];
        const float4* s1 = (const float4*)sm.stage[1];
        float4* o0 = (float4*)(out + 3 * Ns + blk0);
        float4* o1 = (float4*)(out + 5 * Ns + blk0);
        for (int j = tid; j < TILE / 4; j += TPB) { o0[j] = s0[j]; o1[j] = s1[j]; }
    } else {
        for (int j = tid; j < TILE; j += TPB)
            if (j < nrem) { out[3 * Ns + blk0 + j] = sm.stage[0][j]; out[5 * Ns + blk0 + j] = sm.stage[1][j]; }
    }

    float exqx, exqy;
    scanff_fin(&sm, ra, rb, 1, bg + 4u, exqx, exqy);

    // ---- tail: x, y outputs ----
    {
        double basex = sm.c.x0 + (double)exqx;
        float bxhi = (float)basex;
        float bxlo = (float)(basex - (double)bxhi);
        double basey = sm.c.y0 + (double)exqy;
        float byhi = (float)basey;
        float bylo = (float)(basey - (double)byhi);
        float runqx = 0.f, runqy = 0.f;
        __syncthreads();
#pragma unroll
        for (int k = 0; k < EPT; ++k) {
            sm.stage[0][tid * EPT + k] = bxhi + (bxlo + runqx);
            sm.stage[1][tid * EPT + k] = byhi + (bylo + runqy);
            runqx += cxs[k];
            float ypl = fmaf(cyf, (float)(base + k), y0f);
            runqy += qstepf(cyf, ypl);
        }
        __syncthreads();
        if (full) {
            const float4* s0 = (const float4*)sm.stage[0];
            const float4* s1 = (const float4*)sm.stage[1];
            float4* o0 = (float4*)(out + blk0);
            float4* o1 = (float4*)(out + Ns + blk0);
            for (int j = tid; j < TILE / 4; j += TPB) { o0[j] = s0[j]; o1[j] = s1[j]; }
        } else {
            for (int j = tid; j < TILE; j += TPB)
                if (j < nrem) { out[blk0 + j] = sm.stage[0][j]; out[Ns + blk0 + j] = sm.stage[1][j]; }
        }
    }
}

// ---------------- serial fallback (N exceeds capacity) ---------------------
__global__ void __launch_bounds__(32, 1) track_seq_kernel(
    const float* __restrict__ time, const float* __restrict__ r0v,
    const float* __restrict__ d0v, const float* __restrict__ gptr,
    const float* __restrict__ b0ptr, const float* __restrict__ kuptr,
    float* __restrict__ out, int N)
{
    if (threadIdx.x != 0 || blockIdx.x != 0) return;
    const float C = 0.29979245f;
    const float dt = time[1] - time[0];
    const float dt2 = 0.5f * dt, h6 = dt * (1.0f / 6.0f);
    const float gamma = gptr[0], B0 = b0ptr[0], ku = kuptr[0];
    const float A = 1.0f / gamma;
    const float KdtA2 = ku * dt2 * A, KdtA = ku * dt * A;
    const float inv_cg = 1.0f / (C * gamma);
    float dx0 = d0v[0], dy0 = d0v[1], dz0 = d0v[2];
    float dn = sqrtf(dx0 * dx0 + dy0 * dy0 + dz0 * dz0);
    float pscale = C * sqrtf(gamma * gamma - 1.0f) / dn;
    float px = pscale * dx0, py = pscale * dy0, pz = pscale * dz0;
    float x = r0v[0], y = r0v[1], z = r0v[2];
    const float vy = py * A;
    float cps = cosf(ku * z), sps = sinf(ku * z);
    float Bc = B0 * cps, Bs = B0 * sps;
    const size_t Ns = (size_t)N;
    out[0] = x; out[Ns] = y; out[2 * Ns] = z;
    out[3 * Ns] = px * inv_cg; out[4 * Ns] = py * inv_cg; out[5 * Ns] = pz * inv_cg;
#pragma unroll 1
    for (int i = 1; i < N; ++i) {
        float vx1 = px * A, vz1 = pz * A;
        float apx1 = pz * Bc * A, apz1 = -px * Bc * A;
        float px2 = fmaf(apx1, dt2, px), pz2 = fmaf(apz1, dt2, pz);
        float d2 = KdtA2 * pz, q2 = d2 * d2;
        float sd2 = d2 * fmaf(-0.16666667f, q2, 1.0f), cd2 = fmaf(-0.5f, q2, 1.0f);
        float By2 = fmaf(Bc, cd2, -Bs * sd2);
        float vx2 = px2 * A, vz2 = pz2 * A;
        float apx2 = pz2 * By2 * A, apz2 = -px2 * By2 * A;
        float px3 = fmaf(apx2, dt2, px), pz3 = fmaf(apz2, dt2, pz);
        float d3 = KdtA2 * pz2, q3 = d3 * d3;
        float sd3 = d3 * fmaf(-0.16666667f, q3, 1.0f), cd3 = fmaf(-0.5f, q3, 1.0f);
        float By3 = fmaf(Bc, cd3, -Bs * sd3);
        float vx3 = px3 * A, vz3 = pz3 * A;
        float apx3 = pz3 * By3 * A, apz3 = -px3 * By3 * A;
        float px4 = fmaf(apx3, dt, px), pz4 = fmaf(apz3, dt, pz);
        float d4 = KdtA * pz3, q4 = d4 * d4;
        float sd4 = d4 * fmaf(-0.16666667f, q4, 1.0f), cd4 = fmaf(-0.5f, q4, 1.0f);
        float By4 = fmaf(Bc, cd4, -Bs * sd4);
        float vx4 = px4 * A, vz4 = pz4 * A;
        float apx4 = pz4 * By4 * A, apz4 = -px4 * By4 * A;
        float dxs = h6 * (vx1 + 2.0f * (vx2 + vx3) + vx4);
        float dzs = h6 * (vz1 + 2.0f * (vz2 + vz3) + vz4);
        px = px + h6 * (apx1 + 2.0f * (apx2 + apx3) + apx4);
        pz = pz + h6 * (apz1 + 2.0f * (apz2 + apz3) + apz4);
        x += dxs; y += dt * vy; z += dzs;
        float dp = ku * dzs, qp = dp * dp;
        float sdp = dp * fmaf(-0.16666667f, qp, 1.0f), cdp = fmaf(-0.5f, qp, 1.0f);
        float cn = fmaf(cps, cdp, -sps * sdp);
        float sn = fmaf(sps, cdp, cps * sdp);
        float nr = fmaf(cn, cn, sn * sn);
        float corr = fmaf(-0.5f, nr, 1.5f);
        cps = cn * corr; sps = sn * corr;
        Bc = B0 * cps; Bs = B0 * sps;
        out[i] = x; out[Ns + i] = y; out[2 * Ns + i] = z;
        out[3 * Ns + i] = px * inv_cg; out[4 * Ns + i] = py * inv_cg; out[5 * Ns + i] = pz * inv_cg;
    }
}

extern "C" void kernel_launch(void* const* d_in, const int* in_sizes, int n_in,
                              void* d_out, int out_size) {
    const float* time = (const float*)d_in[0];
    const float* r0   = (const float*)d_in[1];
    const float* d0   = (const float*)d_in[2];
    const float* gam  = (const float*)d_in[3];
    const float* B0   = (const float*)d_in[4];
    const float* ku   = (const float*)d_in[5];
    float* out = (float*)d_out;
    int N = in_sizes[0];

    if (N > CAP) {
        track_seq_kernel<<<1, 32>>>(time, r0, d0, gam, B0, ku, out, N);
        return;
    }
    picard_all<<<GRD, TPB>>>(time, r0, d0, gam, B0, ku, out, N);
}